// round 1
// baseline (speedup 1.0000x reference)
#include <cuda_runtime.h>
#include <cuda_bf16.h>
#include <math.h>

// Problem constants
#define BATCH 4
#define LSEQ 1024
#define EMB 1024
#define NH 16
#define DH 64
#define EH (NH*DH)   // 1024

// ---------------- scratch ----------------
// q,k,v: 4M floats each; rp: 1M; att: 4M; o: 4M  => 21M floats = 84MB
__device__ float g_scratch[21u * 1024u * 1024u];

// ---------------- SGEMM: C = A(MxK) @ B(KxN), all row-major, dims % tile == 0 ----------------
#define BM 128
#define BN 128
#define BK 8

__global__ __launch_bounds__(256)
void sgemm_kernel(const float* __restrict__ A, const float* __restrict__ B,
                  float* __restrict__ C, int M, int N, int K) {
    __shared__ float As[BK][BM];
    __shared__ float Bs[BK][BN];

    const int bx = blockIdx.x;   // N tile
    const int by = blockIdx.y;   // M tile
    const int tid = threadIdx.x; // 256
    const int tx = tid & 15;
    const int ty = tid >> 4;

    const float* Ablk = A + (size_t)by * BM * K;
    const float* Bblk = B + (size_t)bx * BN;

    float acc[8][8];
    #pragma unroll
    for (int i = 0; i < 8; i++)
        #pragma unroll
        for (int j = 0; j < 8; j++) acc[i][j] = 0.f;

    const int ar = tid >> 1;           // 0..127
    const int ak = (tid & 1) * 4;      // 0 or 4
    const int br = tid >> 5;           // 0..7
    const int bc = (tid & 31) * 4;     // 0..124

    for (int k0 = 0; k0 < K; k0 += BK) {
        float4 av = *(const float4*)(Ablk + (size_t)ar * K + k0 + ak);
        As[ak + 0][ar] = av.x;
        As[ak + 1][ar] = av.y;
        As[ak + 2][ar] = av.z;
        As[ak + 3][ar] = av.w;
        float4 bv = *(const float4*)(Bblk + (size_t)(k0 + br) * N + bc);
        *(float4*)&Bs[br][bc] = bv;
        __syncthreads();

        #pragma unroll
        for (int k = 0; k < BK; k++) {
            float4 ra0 = *(const float4*)&As[k][ty * 8];
            float4 ra1 = *(const float4*)&As[k][ty * 8 + 4];
            float4 rb0 = *(const float4*)&Bs[k][tx * 8];
            float4 rb1 = *(const float4*)&Bs[k][tx * 8 + 4];
            float ra[8] = {ra0.x, ra0.y, ra0.z, ra0.w, ra1.x, ra1.y, ra1.z, ra1.w};
            float rb[8] = {rb0.x, rb0.y, rb0.z, rb0.w, rb1.x, rb1.y, rb1.z, rb1.w};
            #pragma unroll
            for (int i = 0; i < 8; i++)
                #pragma unroll
                for (int j = 0; j < 8; j++)
                    acc[i][j] += ra[i] * rb[j];
        }
        __syncthreads();
    }

    #pragma unroll
    for (int i = 0; i < 8; i++) {
        float* crow = C + (size_t)(by * BM + ty * 8 + i) * N + bx * BN + tx * 8;
        float4 c0 = {acc[i][0], acc[i][1], acc[i][2], acc[i][3]};
        float4 c1 = {acc[i][4], acc[i][5], acc[i][6], acc[i][7]};
        *(float4*)(crow) = c0;
        *(float4*)(crow + 4) = c1;
    }
}

// ---------------- Attention (flash-style, causal, fused rel-shift) ----------------
// For j<=i: logit = (q_i + rwb)·k_j + (q_i + rrb)·rp[1023 + j - i], scaled by 1/32.
// grid: (16 q-tiles, 16 heads, 4 batch), 256 threads, 64x64 tiles.
// Dynamic smem layout (floats):
//   sQ [64d][64i]  4096
//   sK [64d][64j]  4096
//   sV [64j][64d]  4096
//   sRP[64d][128w] 8192   (window rows 0..126 used)
//   sS [64i][65]   4160
//   sM,sL,sC 64 each; sRWB,sRRB 64 each
#define ATTN_SMEM_FLOATS (4096*3 + 8192 + 64*65 + 5*64)
#define ATTN_SMEM_BYTES  (ATTN_SMEM_FLOATS * 4)

__global__ __launch_bounds__(256)
void attn_kernel(const float* __restrict__ q, const float* __restrict__ k,
                 const float* __restrict__ v, const float* __restrict__ rp,
                 const float* __restrict__ rwb, const float* __restrict__ rrb,
                 float* __restrict__ out) {
    extern __shared__ float smem[];
    float* sQ   = smem;
    float* sK   = sQ + 4096;
    float* sV   = sK + 4096;
    float* sRP  = sV + 4096;
    float* sS   = sRP + 8192;
    float* sM   = sS + 64 * 65;
    float* sL   = sM + 64;
    float* sC   = sL + 64;
    float* sRWB = sC + 64;
    float* sRRB = sRWB + 64;

    const int i0 = blockIdx.x * 64;
    const int n  = blockIdx.y;
    const int b  = blockIdx.z;
    const int tid = threadIdx.x;
    const int tx = tid & 15;
    const int ty = tid >> 4;

    const size_t bq = (size_t)b * LSEQ * EH;

    // load Q tile transposed [d][ii]
    {
        const int jj = tid & 63;
        const int dbase = (tid >> 6) * 16;
        const float* qrow = q + bq + (size_t)(i0 + jj) * EH + n * DH;
        #pragma unroll
        for (int c = 0; c < 4; c++) {
            int d0 = dbase + c * 4;
            float4 val = *(const float4*)(qrow + d0);
            sQ[(d0 + 0) * 64 + jj] = val.x;
            sQ[(d0 + 1) * 64 + jj] = val.y;
            sQ[(d0 + 2) * 64 + jj] = val.z;
            sQ[(d0 + 3) * 64 + jj] = val.w;
        }
    }
    if (tid < 64) {
        sRWB[tid] = rwb[n * DH + tid];
        sRRB[tid] = rrb[n * DH + tid];
        sM[tid] = -1e30f;
        sL[tid] = 0.f;
    }

    float O[4][4];
    #pragma unroll
    for (int a = 0; a < 4; a++)
        #pragma unroll
        for (int bb = 0; bb < 4; bb++) O[a][bb] = 0.f;

    const int w0 = 60 + 4 * (tx - ty);   // rp-window base for this thread's microtile

    for (int j0 = 0; j0 <= i0; j0 += 64) {
        // ---- load K (transposed), V (row-major), RP window (transposed) ----
        {
            const int jj = tid & 63;
            const int dbase = (tid >> 6) * 16;
            const float* krow = k + bq + (size_t)(j0 + jj) * EH + n * DH;
            const float* vrow = v + bq + (size_t)(j0 + jj) * EH + n * DH;
            #pragma unroll
            for (int c = 0; c < 4; c++) {
                int d0 = dbase + c * 4;
                float4 val = *(const float4*)(krow + d0);
                sK[(d0 + 0) * 64 + jj] = val.x;
                sK[(d0 + 1) * 64 + jj] = val.y;
                sK[(d0 + 2) * 64 + jj] = val.z;
                sK[(d0 + 3) * 64 + jj] = val.w;
                *(float4*)(sV + jj * 64 + d0) = *(const float4*)(vrow + d0);
            }
        }
        {
            const int base = 960 - (i0 - j0);  // m = base + w, w in [0,126]
            for (int idx = tid; idx < 127 * 16; idx += 256) {
                int w  = idx % 127;
                int f4 = idx / 127;
                int m = base + w;
                if (m > 1023) m = 1023;  // masked region only; clamp to stay in-bounds
                float4 val = *(const float4*)(rp + (size_t)m * EH + n * DH + f4 * 4);
                sRP[(f4 * 4 + 0) * 128 + w] = val.x;
                sRP[(f4 * 4 + 1) * 128 + w] = val.y;
                sRP[(f4 * 4 + 2) * 128 + w] = val.z;
                sRP[(f4 * 4 + 3) * 128 + w] = val.w;
            }
        }
        __syncthreads();

        // ---- compute S tile ----
        float acc[4][4];
        #pragma unroll
        for (int a = 0; a < 4; a++)
            #pragma unroll
            for (int bb = 0; bb < 4; bb++) acc[a][bb] = 0.f;

        #pragma unroll 4
        for (int d = 0; d < 64; d++) {
            float4 qv = *(const float4*)(sQ + d * 64 + ty * 4);
            float4 kv = *(const float4*)(sK + d * 64 + tx * 4);
            float rwbd = sRWB[d];
            float rrbd = sRRB[d];
            float4 rp0 = *(const float4*)(sRP + d * 128 + w0);
            float4 rp1 = *(const float4*)(sRP + d * 128 + w0 + 4);
            float rpv[8] = {rp0.x, rp0.y, rp0.z, rp0.w, rp1.x, rp1.y, rp1.z, rp1.w};
            float qa[4] = {qv.x, qv.y, qv.z, qv.w};
            float kb[4] = {kv.x, kv.y, kv.z, kv.w};
            #pragma unroll
            for (int a = 0; a < 4; a++) {
                float qw = qa[a] + rwbd;
                float qr = qa[a] + rrbd;
                #pragma unroll
                for (int bb = 0; bb < 4; bb++)
                    acc[a][bb] += qw * kb[bb] + qr * rpv[3 + bb - a];
            }
        }

        // mask + scale + stash to shared
        #pragma unroll
        for (int a = 0; a < 4; a++) {
            int gi = i0 + ty * 4 + a;
            #pragma unroll
            for (int bb = 0; bb < 4; bb++) {
                int gj = j0 + tx * 4 + bb;
                float s = (gj > gi) ? -1e30f : acc[a][bb] * 0.03125f;
                sS[(ty * 4 + a) * 65 + tx * 4 + bb] = s;
            }
        }
        __syncthreads();

        // ---- online softmax (row-wise, 64 threads) ----
        if (tid < 64) {
            float* srow = sS + tid * 65;
            float mold = sM[tid];
            float mx = mold;
            #pragma unroll 8
            for (int j = 0; j < 64; j++) mx = fmaxf(mx, srow[j]);
            float sum = 0.f;
            #pragma unroll 8
            for (int j = 0; j < 64; j++) {
                float p = __expf(srow[j] - mx);
                srow[j] = p;
                sum += p;
            }
            float corr = __expf(mold - mx);
            sL[tid] = sL[tid] * corr + sum;
            sM[tid] = mx;
            sC[tid] = corr;
        }
        __syncthreads();

        // ---- O update: O = O*corr + P @ V ----
        #pragma unroll
        for (int a = 0; a < 4; a++) {
            float c4 = sC[ty * 4 + a];
            #pragma unroll
            for (int bb = 0; bb < 4; bb++) O[a][bb] *= c4;
        }
        #pragma unroll 4
        for (int jj = 0; jj < 64; jj++) {
            float4 vv = *(const float4*)(sV + jj * 64 + tx * 4);
            #pragma unroll
            for (int a = 0; a < 4; a++) {
                float p = sS[(ty * 4 + a) * 65 + jj];
                O[a][0] += p * vv.x;
                O[a][1] += p * vv.y;
                O[a][2] += p * vv.z;
                O[a][3] += p * vv.w;
            }
        }
        __syncthreads();
    }

    // ---- finalize + write out[b, i, n*64 + d] ----
    #pragma unroll
    for (int a = 0; a < 4; a++) {
        int gi = i0 + ty * 4 + a;
        float inv = 1.f / sL[ty * 4 + a];
        float4 o4 = {O[a][0] * inv, O[a][1] * inv, O[a][2] * inv, O[a][3] * inv};
        *(float4*)(out + bq + (size_t)gi * EH + n * DH + tx * 4) = o4;
    }
}

// ---------------- Residual + LayerNorm ----------------
__global__ __launch_bounds__(256)
void ln_kernel(const float* __restrict__ w, const float* __restrict__ o,
               const float* __restrict__ gamma, const float* __restrict__ beta,
               float* __restrict__ out) {
    __shared__ float sh[16];
    __shared__ float mu_s, rstd_s;
    const int row = blockIdx.x;
    const int tid = threadIdx.x;
    const float* wr = w + (size_t)row * EMB;
    const float* orr = o + (size_t)row * EMB;

    float4 xw = *(const float4*)(wr + tid * 4);
    float4 xo = *(const float4*)(orr + tid * 4);
    float x0 = xw.x + xo.x, x1 = xw.y + xo.y, x2 = xw.z + xo.z, x3 = xw.w + xo.w;
    float s = x0 + x1 + x2 + x3;
    float ss = x0 * x0 + x1 * x1 + x2 * x2 + x3 * x3;

    #pragma unroll
    for (int off = 16; off; off >>= 1) {
        s  += __shfl_xor_sync(0xffffffffu, s, off);
        ss += __shfl_xor_sync(0xffffffffu, ss, off);
    }
    if ((tid & 31) == 0) {
        sh[tid >> 5] = s;
        sh[8 + (tid >> 5)] = ss;
    }
    __syncthreads();
    if (tid == 0) {
        float S = 0.f, SS = 0.f;
        #pragma unroll
        for (int i = 0; i < 8; i++) { S += sh[i]; SS += sh[8 + i]; }
        float mu = S * (1.f / 1024.f);
        float var = SS * (1.f / 1024.f) - mu * mu;
        mu_s = mu;
        rstd_s = rsqrtf(var + 1e-3f);
    }
    __syncthreads();

    float mu = mu_s, rstd = rstd_s;
    float4 g4 = *(const float4*)(gamma + tid * 4);
    float4 b4 = *(const float4*)(beta + tid * 4);
    float4 y;
    y.x = (x0 - mu) * rstd * g4.x + b4.x;
    y.y = (x1 - mu) * rstd * g4.y + b4.y;
    y.z = (x2 - mu) * rstd * g4.z + b4.z;
    y.w = (x3 - mu) * rstd * g4.w + b4.w;
    *(float4*)(out + (size_t)row * EMB + tid * 4) = y;
}

// ---------------- launch ----------------
extern "C" void kernel_launch(void* const* d_in, const int* in_sizes, int n_in,
                              void* d_out, int out_size) {
    const float* w     = (const float*)d_in[0];
    const float* r     = (const float*)d_in[1];
    const float* rwb   = (const float*)d_in[2];
    const float* rrb   = (const float*)d_in[3];
    // d_in[4] = attn_mask (causal, implemented analytically)
    const float* Wq    = (const float*)d_in[5];
    const float* Wk    = (const float*)d_in[6];
    const float* Wv    = (const float*)d_in[7];
    const float* Wr    = (const float*)d_in[8];
    const float* Wo    = (const float*)d_in[9];
    const float* gamma = (const float*)d_in[10];
    const float* beta  = (const float*)d_in[11];
    float* outp = (float*)d_out;

    float* base;
    cudaGetSymbolAddress((void**)&base, g_scratch);
    float* gq   = base;
    float* gk   = base + (4u  << 20);
    float* gv   = base + (8u  << 20);
    float* grp  = base + (12u << 20);
    float* gatt = base + (13u << 20);
    float* go   = base + (17u << 20);

    cudaFuncSetAttribute(attn_kernel, cudaFuncAttributeMaxDynamicSharedMemorySize,
                         ATTN_SMEM_BYTES);

    dim3 gBig(EMB / BN, (BATCH * LSEQ) / BM);   // (8, 32)
    dim3 gR(EMB / BN, LSEQ / BM);               // (8, 8)

    sgemm_kernel<<<gBig, 256>>>(w, Wq, gq, BATCH * LSEQ, EMB, EMB);
    sgemm_kernel<<<gBig, 256>>>(w, Wk, gk, BATCH * LSEQ, EMB, EMB);
    sgemm_kernel<<<gBig, 256>>>(w, Wv, gv, BATCH * LSEQ, EMB, EMB);
    sgemm_kernel<<<gR,   256>>>(r, Wr, grp, LSEQ, EMB, EMB);

    attn_kernel<<<dim3(LSEQ / 64, NH, BATCH), 256, ATTN_SMEM_BYTES>>>(
        gq, gk, gv, grp, rwb, rrb, gatt);

    sgemm_kernel<<<gBig, 256>>>(gatt, Wo, go, BATCH * LSEQ, EMB, EMB);
    ln_kernel<<<BATCH * LSEQ, 256>>>(w, go, gamma, beta, outp);
}

// round 3
// speedup vs baseline: 1.4628x; 1.4628x over previous
#include <cuda_runtime.h>
#include <cuda_bf16.h>
#include <math.h>
#include <cstdint>

// Problem constants
#define BATCH 4
#define LSEQ 1024
#define EMB 1024
#define NH 16
#define DH 64
#define EH (NH*DH)   // 1024

// ---------------- scratch ----------------
// q,k,v: 4M each; rp 1M; att 4M; o 4M; 5 transposed weights 5M => 26M floats
__device__ float g_scratch[26u * 1024u * 1024u];

// ================= tf32 mma.sync GEMM =================
// C[M,N] = A[M,K] @ Bt[N,K]^T ; A,Bt row-major (K contiguous).
// CTA tile 128x128, K chunk 32, double-buffered smem, 256 threads (8 warps, 2x4).
#define GBM 128
#define GBN 128
#define GBK 32
#define GPAD 36                       // smem row stride (floats): 36 mod 32 = 4 -> conflict-free frags
#define GBUF (GBM * GPAD)             // one matrix buffer (floats)
#define GEMM_SMEM_BYTES (4 * GBUF * 4)  // A0,B0,A1,B1

__device__ __forceinline__ uint32_t f2tf32(float x) {
    uint32_t r;
    asm("cvt.rna.tf32.f32 %0, %1;" : "=r"(r) : "f"(x));
    return r;
}

__device__ __forceinline__ void mma_tf32(float* c, const uint32_t* a, const uint32_t* b) {
    asm volatile(
        "mma.sync.aligned.m16n8k8.row.col.f32.tf32.tf32.f32 "
        "{%0,%1,%2,%3}, {%4,%5,%6,%7}, {%8,%9}, {%0,%1,%2,%3};"
        : "+f"(c[0]), "+f"(c[1]), "+f"(c[2]), "+f"(c[3])
        : "r"(a[0]), "r"(a[1]), "r"(a[2]), "r"(a[3]), "r"(b[0]), "r"(b[1]));
}

__global__ __launch_bounds__(256)
void tgemm_kernel(const float* __restrict__ A, const float* __restrict__ Bt,
                  float* __restrict__ C, int M, int N, int K) {
    extern __shared__ uint32_t gsm[];
    uint32_t* sA[2] = {gsm, gsm + 2 * GBUF};
    uint32_t* sB[2] = {gsm + GBUF, gsm + 3 * GBUF};

    const int tid = threadIdx.x;
    const int wid = tid >> 5;
    const int lane = tid & 31;
    const int g = lane >> 2;       // group (row within fragment)
    const int t = lane & 3;        // thread-in-group (col within fragment)
    const int wm = wid >> 2;       // 0..1
    const int wn = wid & 3;        // 0..3
    const int n0 = blockIdx.x * GBN;
    const int m0 = blockIdx.y * GBM;

    const float* Ab = A + (size_t)m0 * K;
    const float* Bb = Bt + (size_t)n0 * K;
    const int nstages = K / GBK;

    float acc[4][4][4];
    #pragma unroll
    for (int mi = 0; mi < 4; mi++)
        #pragma unroll
        for (int ni = 0; ni < 4; ni++)
            #pragma unroll
            for (int r = 0; r < 4; r++) acc[mi][ni][r] = 0.f;

    // per-thread staging registers for gmem->smem
    float4 stA[4], stB[4];

    // thread's copy mapping: idx = tid + 256*i -> row = idx>>3, c4 = idx&7
    auto load_stage = [&](int s) {
        const int k0 = s * GBK;
        #pragma unroll
        for (int i = 0; i < 4; i++) {
            const int idx = tid + 256 * i;
            const int r = idx >> 3;
            const int c4 = (idx & 7) * 4;
            stA[i] = *(const float4*)(Ab + (size_t)r * K + k0 + c4);
            stB[i] = *(const float4*)(Bb + (size_t)r * K + k0 + c4);
        }
    };
    auto store_stage = [&](int buf) {
        #pragma unroll
        for (int i = 0; i < 4; i++) {
            const int idx = tid + 256 * i;
            const int r = idx >> 3;
            const int c4 = (idx & 7) * 4;
            uint32_t* pa = sA[buf] + r * GPAD + c4;
            pa[0] = f2tf32(stA[i].x); pa[1] = f2tf32(stA[i].y);
            pa[2] = f2tf32(stA[i].z); pa[3] = f2tf32(stA[i].w);
            uint32_t* pb = sB[buf] + r * GPAD + c4;
            pb[0] = f2tf32(stB[i].x); pb[1] = f2tf32(stB[i].y);
            pb[2] = f2tf32(stB[i].z); pb[3] = f2tf32(stB[i].w);
        }
    };

    load_stage(0);
    store_stage(0);
    __syncthreads();

    for (int s = 0; s < nstages; s++) {
        const int buf = s & 1;
        if (s + 1 < nstages) load_stage(s + 1);

        const uint32_t* As = sA[buf];
        const uint32_t* Bs = sB[buf];
        #pragma unroll
        for (int kk = 0; kk < GBK; kk += 8) {
            uint32_t af[4][4], bf[4][2];
            #pragma unroll
            for (int mi = 0; mi < 4; mi++) {
                const int row0 = wm * 64 + mi * 16 + g;
                af[mi][0] = As[row0 * GPAD + kk + t];
                af[mi][1] = As[(row0 + 8) * GPAD + kk + t];
                af[mi][2] = As[row0 * GPAD + kk + t + 4];
                af[mi][3] = As[(row0 + 8) * GPAD + kk + t + 4];
            }
            #pragma unroll
            for (int ni = 0; ni < 4; ni++) {
                const int col0 = wn * 32 + ni * 8 + g;
                bf[ni][0] = Bs[col0 * GPAD + kk + t];
                bf[ni][1] = Bs[col0 * GPAD + kk + t + 4];
            }
            #pragma unroll
            for (int mi = 0; mi < 4; mi++)
                #pragma unroll
                for (int ni = 0; ni < 4; ni++)
                    mma_tf32(acc[mi][ni], af[mi], bf[ni]);
        }

        if (s + 1 < nstages) {
            store_stage((s + 1) & 1);
            __syncthreads();
        }
    }

    // epilogue: direct float2 stores
    #pragma unroll
    for (int mi = 0; mi < 4; mi++) {
        const int row0 = m0 + wm * 64 + mi * 16 + g;
        #pragma unroll
        for (int ni = 0; ni < 4; ni++) {
            const int col = n0 + wn * 32 + ni * 8 + 2 * t;
            float2 v0 = {acc[mi][ni][0], acc[mi][ni][1]};
            float2 v1 = {acc[mi][ni][2], acc[mi][ni][3]};
            *(float2*)(C + (size_t)row0 * N + col) = v0;
            *(float2*)(C + (size_t)(row0 + 8) * N + col) = v1;
        }
    }
}

// ================= 1024x1024 transpose =================
__global__ __launch_bounds__(256)
void transpose1k(const float* __restrict__ S, float* __restrict__ D) {
    __shared__ float t[32][33];
    const int x = blockIdx.x * 32 + threadIdx.x;
    const int y0 = blockIdx.y * 32;
    #pragma unroll
    for (int i = threadIdx.y; i < 32; i += 8)
        t[i][threadIdx.x] = S[(size_t)(y0 + i) * 1024 + x];
    __syncthreads();
    const int xo = y0 + threadIdx.x;
    #pragma unroll
    for (int i = threadIdx.y; i < 32; i += 8)
        D[(size_t)(blockIdx.x * 32 + i) * 1024 + xo] = t[threadIdx.x][i];
}

// ---------------- Attention (flash-style, causal, fused rel-shift) ----------------
#define ATTN_SMEM_FLOATS (4096*3 + 8192 + 64*65 + 5*64)
#define ATTN_SMEM_BYTES  (ATTN_SMEM_FLOATS * 4)

__global__ __launch_bounds__(256)
void attn_kernel(const float* __restrict__ q, const float* __restrict__ k,
                 const float* __restrict__ v, const float* __restrict__ rp,
                 const float* __restrict__ rwb, const float* __restrict__ rrb,
                 float* __restrict__ out) {
    extern __shared__ float smem[];
    float* sQ   = smem;
    float* sK   = sQ + 4096;
    float* sV   = sK + 4096;
    float* sRP  = sV + 4096;
    float* sS   = sRP + 8192;
    float* sM   = sS + 64 * 65;
    float* sL   = sM + 64;
    float* sC   = sL + 64;
    float* sRWB = sC + 64;
    float* sRRB = sRWB + 64;

    const int i0 = blockIdx.x * 64;
    const int n  = blockIdx.y;
    const int b  = blockIdx.z;
    const int tid = threadIdx.x;
    const int tx = tid & 15;
    const int ty = tid >> 4;

    const size_t bq = (size_t)b * LSEQ * EH;

    {
        const int jj = tid & 63;
        const int dbase = (tid >> 6) * 16;
        const float* qrow = q + bq + (size_t)(i0 + jj) * EH + n * DH;
        #pragma unroll
        for (int c = 0; c < 4; c++) {
            int d0 = dbase + c * 4;
            float4 val = *(const float4*)(qrow + d0);
            sQ[(d0 + 0) * 64 + jj] = val.x;
            sQ[(d0 + 1) * 64 + jj] = val.y;
            sQ[(d0 + 2) * 64 + jj] = val.z;
            sQ[(d0 + 3) * 64 + jj] = val.w;
        }
    }
    if (tid < 64) {
        sRWB[tid] = rwb[n * DH + tid];
        sRRB[tid] = rrb[n * DH + tid];
        sM[tid] = -1e30f;
        sL[tid] = 0.f;
    }

    float O[4][4];
    #pragma unroll
    for (int a = 0; a < 4; a++)
        #pragma unroll
        for (int bb = 0; bb < 4; bb++) O[a][bb] = 0.f;

    const int w0 = 60 + 4 * (tx - ty);

    for (int j0 = 0; j0 <= i0; j0 += 64) {
        {
            const int jj = tid & 63;
            const int dbase = (tid >> 6) * 16;
            const float* krow = k + bq + (size_t)(j0 + jj) * EH + n * DH;
            const float* vrow = v + bq + (size_t)(j0 + jj) * EH + n * DH;
            #pragma unroll
            for (int c = 0; c < 4; c++) {
                int d0 = dbase + c * 4;
                float4 val = *(const float4*)(krow + d0);
                sK[(d0 + 0) * 64 + jj] = val.x;
                sK[(d0 + 1) * 64 + jj] = val.y;
                sK[(d0 + 2) * 64 + jj] = val.z;
                sK[(d0 + 3) * 64 + jj] = val.w;
                *(float4*)(sV + jj * 64 + d0) = *(const float4*)(vrow + d0);
            }
        }
        {
            const int base = 960 - (i0 - j0);
            for (int idx = tid; idx < 127 * 16; idx += 256) {
                int w  = idx % 127;
                int f4 = idx / 127;
                int m = base + w;
                if (m > 1023) m = 1023;
                float4 val = *(const float4*)(rp + (size_t)m * EH + n * DH + f4 * 4);
                sRP[(f4 * 4 + 0) * 128 + w] = val.x;
                sRP[(f4 * 4 + 1) * 128 + w] = val.y;
                sRP[(f4 * 4 + 2) * 128 + w] = val.z;
                sRP[(f4 * 4 + 3) * 128 + w] = val.w;
            }
        }
        __syncthreads();

        float acc[4][4];
        #pragma unroll
        for (int a = 0; a < 4; a++)
            #pragma unroll
            for (int bb = 0; bb < 4; bb++) acc[a][bb] = 0.f;

        #pragma unroll 4
        for (int d = 0; d < 64; d++) {
            float4 qv = *(const float4*)(sQ + d * 64 + ty * 4);
            float4 kv = *(const float4*)(sK + d * 64 + tx * 4);
            float rwbd = sRWB[d];
            float rrbd = sRRB[d];
            float4 rp0 = *(const float4*)(sRP + d * 128 + w0);
            float4 rp1 = *(const float4*)(sRP + d * 128 + w0 + 4);
            float rpv[8] = {rp0.x, rp0.y, rp0.z, rp0.w, rp1.x, rp1.y, rp1.z, rp1.w};
            float qa[4] = {qv.x, qv.y, qv.z, qv.w};
            float kb[4] = {kv.x, kv.y, kv.z, kv.w};
            #pragma unroll
            for (int a = 0; a < 4; a++) {
                float qw = qa[a] + rwbd;
                float qr = qa[a] + rrbd;
                #pragma unroll
                for (int bb = 0; bb < 4; bb++)
                    acc[a][bb] += qw * kb[bb] + qr * rpv[3 + bb - a];
            }
        }

        #pragma unroll
        for (int a = 0; a < 4; a++) {
            int gi = i0 + ty * 4 + a;
            #pragma unroll
            for (int bb = 0; bb < 4; bb++) {
                int gj = j0 + tx * 4 + bb;
                float s = (gj > gi) ? -1e30f : acc[a][bb] * 0.03125f;
                sS[(ty * 4 + a) * 65 + tx * 4 + bb] = s;
            }
        }
        __syncthreads();

        if (tid < 64) {
            float* srow = sS + tid * 65;
            float mold = sM[tid];
            float mx = mold;
            #pragma unroll 8
            for (int j = 0; j < 64; j++) mx = fmaxf(mx, srow[j]);
            float sum = 0.f;
            #pragma unroll 8
            for (int j = 0; j < 64; j++) {
                float p = __expf(srow[j] - mx);
                srow[j] = p;
                sum += p;
            }
            float corr = __expf(mold - mx);
            sL[tid] = sL[tid] * corr + sum;
            sM[tid] = mx;
            sC[tid] = corr;
        }
        __syncthreads();

        #pragma unroll
        for (int a = 0; a < 4; a++) {
            float c4 = sC[ty * 4 + a];
            #pragma unroll
            for (int bb = 0; bb < 4; bb++) O[a][bb] *= c4;
        }
        #pragma unroll 4
        for (int jj = 0; jj < 64; jj++) {
            float4 vv = *(const float4*)(sV + jj * 64 + tx * 4);
            #pragma unroll
            for (int a = 0; a < 4; a++) {
                float p = sS[(ty * 4 + a) * 65 + jj];
                O[a][0] += p * vv.x;
                O[a][1] += p * vv.y;
                O[a][2] += p * vv.z;
                O[a][3] += p * vv.w;
            }
        }
        __syncthreads();
    }

    #pragma unroll
    for (int a = 0; a < 4; a++) {
        int gi = i0 + ty * 4 + a;
        float inv = 1.f / sL[ty * 4 + a];
        float4 o4 = {O[a][0] * inv, O[a][1] * inv, O[a][2] * inv, O[a][3] * inv};
        *(float4*)(out + bq + (size_t)gi * EH + n * DH + tx * 4) = o4;
    }
}

// ---------------- Residual + LayerNorm ----------------
__global__ __launch_bounds__(256)
void ln_kernel(const float* __restrict__ w, const float* __restrict__ o,
               const float* __restrict__ gamma, const float* __restrict__ beta,
               float* __restrict__ out) {
    __shared__ float sh[16];
    __shared__ float mu_s, rstd_s;
    const int row = blockIdx.x;
    const int tid = threadIdx.x;
    const float* wr = w + (size_t)row * EMB;
    const float* orr = o + (size_t)row * EMB;

    float4 xw = *(const float4*)(wr + tid * 4);
    float4 xo = *(const float4*)(orr + tid * 4);
    float x0 = xw.x + xo.x, x1 = xw.y + xo.y, x2 = xw.z + xo.z, x3 = xw.w + xo.w;
    float s = x0 + x1 + x2 + x3;
    float ss = x0 * x0 + x1 * x1 + x2 * x2 + x3 * x3;

    #pragma unroll
    for (int off = 16; off; off >>= 1) {
        s  += __shfl_xor_sync(0xffffffffu, s, off);
        ss += __shfl_xor_sync(0xffffffffu, ss, off);
    }
    if ((tid & 31) == 0) {
        sh[tid >> 5] = s;
        sh[8 + (tid >> 5)] = ss;
    }
    __syncthreads();
    if (tid == 0) {
        float S = 0.f, SS = 0.f;
        #pragma unroll
        for (int i = 0; i < 8; i++) { S += sh[i]; SS += sh[8 + i]; }
        float mu = S * (1.f / 1024.f);
        float var = SS * (1.f / 1024.f) - mu * mu;
        mu_s = mu;
        rstd_s = rsqrtf(var + 1e-3f);
    }
    __syncthreads();

    float mu = mu_s, rstd = rstd_s;
    float4 g4 = *(const float4*)(gamma + tid * 4);
    float4 b4 = *(const float4*)(beta + tid * 4);
    float4 y;
    y.x = (x0 - mu) * rstd * g4.x + b4.x;
    y.y = (x1 - mu) * rstd * g4.y + b4.y;
    y.z = (x2 - mu) * rstd * g4.z + b4.z;
    y.w = (x3 - mu) * rstd * g4.w + b4.w;
    *(float4*)(out + (size_t)row * EMB + tid * 4) = y;
}

// ---------------- launch ----------------
extern "C" void kernel_launch(void* const* d_in, const int* in_sizes, int n_in,
                              void* d_out, int out_size) {
    const float* w     = (const float*)d_in[0];
    const float* r     = (const float*)d_in[1];
    const float* rwb   = (const float*)d_in[2];
    const float* rrb   = (const float*)d_in[3];
    // d_in[4] = attn_mask (causal, analytic)
    const float* Wq    = (const float*)d_in[5];
    const float* Wk    = (const float*)d_in[6];
    const float* Wv    = (const float*)d_in[7];
    const float* Wr    = (const float*)d_in[8];
    const float* Wo    = (const float*)d_in[9];
    const float* gamma = (const float*)d_in[10];
    const float* beta  = (const float*)d_in[11];
    float* outp = (float*)d_out;

    float* base;
    cudaGetSymbolAddress((void**)&base, g_scratch);
    float* gq   = base;
    float* gk   = base + (4u  << 20);
    float* gv   = base + (8u  << 20);
    float* grp  = base + (12u << 20);
    float* gatt = base + (13u << 20);
    float* go   = base + (17u << 20);
    float* WqT  = base + (21u << 20);
    float* WkT  = base + (22u << 20);
    float* WvT  = base + (23u << 20);
    float* WrT  = base + (24u << 20);
    float* WoT  = base + (25u << 20);

    cudaFuncSetAttribute(attn_kernel, cudaFuncAttributeMaxDynamicSharedMemorySize,
                         ATTN_SMEM_BYTES);
    cudaFuncSetAttribute(tgemm_kernel, cudaFuncAttributeMaxDynamicSharedMemorySize,
                         GEMM_SMEM_BYTES);

    dim3 tgrid(32, 32);
    dim3 tblk(32, 8);
    transpose1k<<<tgrid, tblk>>>(Wq, WqT);
    transpose1k<<<tgrid, tblk>>>(Wk, WkT);
    transpose1k<<<tgrid, tblk>>>(Wv, WvT);
    transpose1k<<<tgrid, tblk>>>(Wr, WrT);
    transpose1k<<<tgrid, tblk>>>(Wo, WoT);

    dim3 gBig(EMB / 128, (BATCH * LSEQ) / 128);  // (8, 32)
    dim3 gR(EMB / 128, LSEQ / 128);              // (8, 8)

    tgemm_kernel<<<gBig, 256, GEMM_SMEM_BYTES>>>(w, WqT, gq, BATCH * LSEQ, EMB, EMB);
    tgemm_kernel<<<gBig, 256, GEMM_SMEM_BYTES>>>(w, WkT, gk, BATCH * LSEQ, EMB, EMB);
    tgemm_kernel<<<gBig, 256, GEMM_SMEM_BYTES>>>(w, WvT, gv, BATCH * LSEQ, EMB, EMB);
    tgemm_kernel<<<gR,   256, GEMM_SMEM_BYTES>>>(r, WrT, grp, LSEQ, EMB, EMB);

    attn_kernel<<<dim3(LSEQ / 64, NH, BATCH), 256, ATTN_SMEM_BYTES>>>(
        gq, gk, gv, grp, rwb, rrb, gatt);

    tgemm_kernel<<<gBig, 256, GEMM_SMEM_BYTES>>>(gatt, WoT, go, BATCH * LSEQ, EMB, EMB);
    ln_kernel<<<BATCH * LSEQ, 256>>>(w, go, gamma, beta, outp);
}

// round 4
// speedup vs baseline: 1.7868x; 1.2215x over previous
#include <cuda_runtime.h>
#include <cuda_bf16.h>
#include <math.h>
#include <cstdint>

// Problem constants
#define BATCH 4
#define LSEQ 1024
#define EMB 1024
#define NH 16
#define DH 64
#define EH (NH*DH)   // 1024

// ---------------- scratch ----------------
// q,k,v: 4M each; rp 1M; att 4M; o 4M => 21M floats
__device__ float g_scratch[21u * 1024u * 1024u];

// ================= tf32 mma.sync GEMM with cp.async =================
// C[M,N] = A[M,K] @ B[K,N] ; A,B row-major. Tiles: 128x128x32, 3-stage cp.async.
#define GBM 128
#define GBN 128
#define GBK 32
#define NSTG 3
#define APAD 36                        // A smem row stride (floats)
#define BPAD 136                       // B smem row stride (floats)
#define A_STG (GBM * APAD)             // floats per A stage = 4608
#define B_STG (GBK * BPAD)             // floats per B stage = 4352
#define STG_FLOATS (A_STG + B_STG)     // 8960 floats = 35840 B
#define GEMM_SMEM_BYTES (NSTG * STG_FLOATS * 4)   // 107520 B

__device__ __forceinline__ uint32_t smem_u32(const void* p) {
    uint32_t a;
    asm("{ .reg .u64 t; cvta.to.shared.u64 t, %1; cvt.u32.u64 %0, t; }" : "=r"(a) : "l"(p));
    return a;
}
__device__ __forceinline__ void cp16(uint32_t dst, const void* src) {
    asm volatile("cp.async.cg.shared.global [%0], [%1], 16;" :: "r"(dst), "l"(src));
}
#define CP_COMMIT() asm volatile("cp.async.commit_group;" ::: "memory")
#define CP_WAIT1()  asm volatile("cp.async.wait_group 1;" ::: "memory")

__device__ __forceinline__ void mma_tf32(float* c, const uint32_t* a, const uint32_t* b) {
    asm volatile(
        "mma.sync.aligned.m16n8k8.row.col.f32.tf32.tf32.f32 "
        "{%0,%1,%2,%3}, {%4,%5,%6,%7}, {%8,%9}, {%0,%1,%2,%3};"
        : "+f"(c[0]), "+f"(c[1]), "+f"(c[2]), "+f"(c[3])
        : "r"(a[0]), "r"(a[1]), "r"(a[2]), "r"(a[3]), "r"(b[0]), "r"(b[1]));
}

__global__ __launch_bounds__(256, 2)
void tgemm_kernel(const float* __restrict__ A, const float* __restrict__ B,
                  float* __restrict__ C, int M, int N, int K) {
    extern __shared__ uint32_t gsm[];
    const uint32_t sb = smem_u32(gsm);

    const int tid = threadIdx.x;
    const int wid = tid >> 5;
    const int lane = tid & 31;
    const int g = lane >> 2;
    const int t = lane & 3;
    const int wm = wid >> 2;       // 0..1
    const int wn = wid & 3;        // 0..3
    const int n0 = blockIdx.x * GBN;
    const int m0 = blockIdx.y * GBM;

    const float* Ab = A + (size_t)m0 * K;
    const float* Bb = B + n0;
    const int nstages = K / GBK;

    // per-thread copy mappings
    const int ar = tid >> 1;                 // A: 2 chunks/row? no: idx scheme below
    (void)ar;

    auto issue = [&](int s) {
        const int k0 = s * GBK;
        const uint32_t abase = sb + (uint32_t)((s % NSTG) * STG_FLOATS * 4);
        const uint32_t bbase = abase + A_STG * 4;
        // A tile: 128 rows x 32 floats = 1024 x 16B chunks
        #pragma unroll
        for (int i = 0; i < 4; i++) {
            const int idx = tid + 256 * i;
            const int r = idx >> 3;
            const int c = idx & 7;
            cp16(abase + (uint32_t)(r * (APAD * 4) + c * 16),
                 Ab + (size_t)r * K + k0 + c * 4);
        }
        // B tile: 32 rows x 128 floats = 1024 x 16B chunks
        #pragma unroll
        for (int i = 0; i < 4; i++) {
            const int idx = tid + 256 * i;
            const int r = idx >> 5;
            const int c = idx & 31;
            cp16(bbase + (uint32_t)(r * (BPAD * 4) + c * 16),
                 Bb + (size_t)(k0 + r) * N + c * 4);
        }
        CP_COMMIT();
    };

    float acc[4][4][4];
    #pragma unroll
    for (int mi = 0; mi < 4; mi++)
        #pragma unroll
        for (int ni = 0; ni < 4; ni++)
            #pragma unroll
            for (int r = 0; r < 4; r++) acc[mi][ni][r] = 0.f;

    issue(0);
    issue(1);

    for (int s = 0; s < nstages; s++) {
        CP_WAIT1();
        __syncthreads();
        if (s + 2 < nstages) issue(s + 2);

        const uint32_t* As = gsm + (s % NSTG) * STG_FLOATS;
        const uint32_t* Bs = As + A_STG;

        #pragma unroll
        for (int kk = 0; kk < GBK; kk += 8) {
            uint32_t af[4][4], bf[4][2];
            #pragma unroll
            for (int mi = 0; mi < 4; mi++) {
                const int row0 = wm * 64 + mi * 16 + g;
                af[mi][0] = As[row0 * APAD + kk + t];
                af[mi][1] = As[(row0 + 8) * APAD + kk + t];
                af[mi][2] = As[row0 * APAD + kk + t + 4];
                af[mi][3] = As[(row0 + 8) * APAD + kk + t + 4];
            }
            #pragma unroll
            for (int ni = 0; ni < 4; ni++) {
                const int col0 = wn * 32 + ni * 8 + g;
                bf[ni][0] = Bs[(kk + t) * BPAD + col0];
                bf[ni][1] = Bs[(kk + t + 4) * BPAD + col0];
            }
            #pragma unroll
            for (int mi = 0; mi < 4; mi++)
                #pragma unroll
                for (int ni = 0; ni < 4; ni++)
                    mma_tf32(acc[mi][ni], af[mi], bf[ni]);
        }
        __syncthreads();
    }

    #pragma unroll
    for (int mi = 0; mi < 4; mi++) {
        const int row0 = m0 + wm * 64 + mi * 16 + g;
        #pragma unroll
        for (int ni = 0; ni < 4; ni++) {
            const int col = n0 + wn * 32 + ni * 8 + 2 * t;
            float2 v0 = {acc[mi][ni][0], acc[mi][ni][1]};
            float2 v1 = {acc[mi][ni][2], acc[mi][ni][3]};
            *(float2*)(C + (size_t)row0 * N + col) = v0;
            *(float2*)(C + (size_t)(row0 + 8) * N + col) = v1;
        }
    }
}

// ---------------- Attention (flash-style, causal, fused rel-shift) ----------------
#define ATTN_SMEM_FLOATS (4096*3 + 8192 + 64*65 + 5*64)
#define ATTN_SMEM_BYTES  (ATTN_SMEM_FLOATS * 4)

__global__ __launch_bounds__(256)
void attn_kernel(const float* __restrict__ q, const float* __restrict__ k,
                 const float* __restrict__ v, const float* __restrict__ rp,
                 const float* __restrict__ rwb, const float* __restrict__ rrb,
                 float* __restrict__ out) {
    extern __shared__ float smem[];
    float* sQ   = smem;
    float* sK   = sQ + 4096;
    float* sV   = sK + 4096;
    float* sRP  = sV + 4096;
    float* sS   = sRP + 8192;
    float* sM   = sS + 64 * 65;
    float* sL   = sM + 64;
    float* sC   = sL + 64;
    float* sRWB = sC + 64;
    float* sRRB = sRWB + 64;

    const int i0 = blockIdx.x * 64;
    const int n  = blockIdx.y;
    const int b  = blockIdx.z;
    const int tid = threadIdx.x;
    const int tx = tid & 15;
    const int ty = tid >> 4;

    const size_t bq = (size_t)b * LSEQ * EH;

    {
        const int jj = tid & 63;
        const int dbase = (tid >> 6) * 16;
        const float* qrow = q + bq + (size_t)(i0 + jj) * EH + n * DH;
        #pragma unroll
        for (int c = 0; c < 4; c++) {
            int d0 = dbase + c * 4;
            float4 val = *(const float4*)(qrow + d0);
            sQ[(d0 + 0) * 64 + jj] = val.x;
            sQ[(d0 + 1) * 64 + jj] = val.y;
            sQ[(d0 + 2) * 64 + jj] = val.z;
            sQ[(d0 + 3) * 64 + jj] = val.w;
        }
    }
    if (tid < 64) {
        sRWB[tid] = rwb[n * DH + tid];
        sRRB[tid] = rrb[n * DH + tid];
        sM[tid] = -1e30f;
        sL[tid] = 0.f;
    }

    float O[4][4];
    #pragma unroll
    for (int a = 0; a < 4; a++)
        #pragma unroll
        for (int bb = 0; bb < 4; bb++) O[a][bb] = 0.f;

    const int w0 = 60 + 4 * (tx - ty);

    for (int j0 = 0; j0 <= i0; j0 += 64) {
        {
            const int jj = tid & 63;
            const int dbase = (tid >> 6) * 16;
            const float* krow = k + bq + (size_t)(j0 + jj) * EH + n * DH;
            const float* vrow = v + bq + (size_t)(j0 + jj) * EH + n * DH;
            #pragma unroll
            for (int c = 0; c < 4; c++) {
                int d0 = dbase + c * 4;
                float4 val = *(const float4*)(krow + d0);
                sK[(d0 + 0) * 64 + jj] = val.x;
                sK[(d0 + 1) * 64 + jj] = val.y;
                sK[(d0 + 2) * 64 + jj] = val.z;
                sK[(d0 + 3) * 64 + jj] = val.w;
                *(float4*)(sV + jj * 64 + d0) = *(const float4*)(vrow + d0);
            }
        }
        {
            const int base = 960 - (i0 - j0);
            for (int idx = tid; idx < 127 * 16; idx += 256) {
                int w  = idx % 127;
                int f4 = idx / 127;
                int m = base + w;
                if (m > 1023) m = 1023;
                float4 val = *(const float4*)(rp + (size_t)m * EH + n * DH + f4 * 4);
                sRP[(f4 * 4 + 0) * 128 + w] = val.x;
                sRP[(f4 * 4 + 1) * 128 + w] = val.y;
                sRP[(f4 * 4 + 2) * 128 + w] = val.z;
                sRP[(f4 * 4 + 3) * 128 + w] = val.w;
            }
        }
        __syncthreads();

        float acc[4][4];
        #pragma unroll
        for (int a = 0; a < 4; a++)
            #pragma unroll
            for (int bb = 0; bb < 4; bb++) acc[a][bb] = 0.f;

        #pragma unroll 4
        for (int d = 0; d < 64; d++) {
            float4 qv = *(const float4*)(sQ + d * 64 + ty * 4);
            float4 kv = *(const float4*)(sK + d * 64 + tx * 4);
            float rwbd = sRWB[d];
            float rrbd = sRRB[d];
            float4 rp0 = *(const float4*)(sRP + d * 128 + w0);
            float4 rp1 = *(const float4*)(sRP + d * 128 + w0 + 4);
            float rpv[8] = {rp0.x, rp0.y, rp0.z, rp0.w, rp1.x, rp1.y, rp1.z, rp1.w};
            float qa[4] = {qv.x, qv.y, qv.z, qv.w};
            float kb[4] = {kv.x, kv.y, kv.z, kv.w};
            #pragma unroll
            for (int a = 0; a < 4; a++) {
                float qw = qa[a] + rwbd;
                float qr = qa[a] + rrbd;
                #pragma unroll
                for (int bb = 0; bb < 4; bb++)
                    acc[a][bb] += qw * kb[bb] + qr * rpv[3 + bb - a];
            }
        }

        #pragma unroll
        for (int a = 0; a < 4; a++) {
            int gi = i0 + ty * 4 + a;
            #pragma unroll
            for (int bb = 0; bb < 4; bb++) {
                int gj = j0 + tx * 4 + bb;
                float s = (gj > gi) ? -1e30f : acc[a][bb] * 0.03125f;
                sS[(ty * 4 + a) * 65 + tx * 4 + bb] = s;
            }
        }
        __syncthreads();

        if (tid < 64) {
            float* srow = sS + tid * 65;
            float mold = sM[tid];
            float mx = mold;
            #pragma unroll 8
            for (int j = 0; j < 64; j++) mx = fmaxf(mx, srow[j]);
            float sum = 0.f;
            #pragma unroll 8
            for (int j = 0; j < 64; j++) {
                float p = __expf(srow[j] - mx);
                srow[j] = p;
                sum += p;
            }
            float corr = __expf(mold - mx);
            sL[tid] = sL[tid] * corr + sum;
            sM[tid] = mx;
            sC[tid] = corr;
        }
        __syncthreads();

        #pragma unroll
        for (int a = 0; a < 4; a++) {
            float c4 = sC[ty * 4 + a];
            #pragma unroll
            for (int bb = 0; bb < 4; bb++) O[a][bb] *= c4;
        }
        #pragma unroll 4
        for (int jj = 0; jj < 64; jj++) {
            float4 vv = *(const float4*)(sV + jj * 64 + tx * 4);
            #pragma unroll
            for (int a = 0; a < 4; a++) {
                float p = sS[(ty * 4 + a) * 65 + jj];
                O[a][0] += p * vv.x;
                O[a][1] += p * vv.y;
                O[a][2] += p * vv.z;
                O[a][3] += p * vv.w;
            }
        }
        __syncthreads();
    }

    #pragma unroll
    for (int a = 0; a < 4; a++) {
        int gi = i0 + ty * 4 + a;
        float inv = 1.f / sL[ty * 4 + a];
        float4 o4 = {O[a][0] * inv, O[a][1] * inv, O[a][2] * inv, O[a][3] * inv};
        *(float4*)(out + bq + (size_t)gi * EH + n * DH + tx * 4) = o4;
    }
}

// ---------------- Residual + LayerNorm ----------------
__global__ __launch_bounds__(256)
void ln_kernel(const float* __restrict__ w, const float* __restrict__ o,
               const float* __restrict__ gamma, const float* __restrict__ beta,
               float* __restrict__ out) {
    __shared__ float sh[16];
    __shared__ float mu_s, rstd_s;
    const int row = blockIdx.x;
    const int tid = threadIdx.x;
    const float* wr = w + (size_t)row * EMB;
    const float* orr = o + (size_t)row * EMB;

    float4 xw = *(const float4*)(wr + tid * 4);
    float4 xo = *(const float4*)(orr + tid * 4);
    float x0 = xw.x + xo.x, x1 = xw.y + xo.y, x2 = xw.z + xo.z, x3 = xw.w + xo.w;
    float s = x0 + x1 + x2 + x3;
    float ss = x0 * x0 + x1 * x1 + x2 * x2 + x3 * x3;

    #pragma unroll
    for (int off = 16; off; off >>= 1) {
        s  += __shfl_xor_sync(0xffffffffu, s, off);
        ss += __shfl_xor_sync(0xffffffffu, ss, off);
    }
    if ((tid & 31) == 0) {
        sh[tid >> 5] = s;
        sh[8 + (tid >> 5)] = ss;
    }
    __syncthreads();
    if (tid == 0) {
        float S = 0.f, SS = 0.f;
        #pragma unroll
        for (int i = 0; i < 8; i++) { S += sh[i]; SS += sh[8 + i]; }
        float mu = S * (1.f / 1024.f);
        float var = SS * (1.f / 1024.f) - mu * mu;
        mu_s = mu;
        rstd_s = rsqrtf(var + 1e-3f);
    }
    __syncthreads();

    float mu = mu_s, rstd = rstd_s;
    float4 g4 = *(const float4*)(gamma + tid * 4);
    float4 b4 = *(const float4*)(beta + tid * 4);
    float4 y;
    y.x = (x0 - mu) * rstd * g4.x + b4.x;
    y.y = (x1 - mu) * rstd * g4.y + b4.y;
    y.z = (x2 - mu) * rstd * g4.z + b4.z;
    y.w = (x3 - mu) * rstd * g4.w + b4.w;
    *(float4*)(out + (size_t)row * EMB + tid * 4) = y;
}

// ---------------- launch ----------------
extern "C" void kernel_launch(void* const* d_in, const int* in_sizes, int n_in,
                              void* d_out, int out_size) {
    const float* w     = (const float*)d_in[0];
    const float* r     = (const float*)d_in[1];
    const float* rwb   = (const float*)d_in[2];
    const float* rrb   = (const float*)d_in[3];
    // d_in[4] = attn_mask (causal, analytic)
    const float* Wq    = (const float*)d_in[5];
    const float* Wk    = (const float*)d_in[6];
    const float* Wv    = (const float*)d_in[7];
    const float* Wr    = (const float*)d_in[8];
    const float* Wo    = (const float*)d_in[9];
    const float* gamma = (const float*)d_in[10];
    const float* beta  = (const float*)d_in[11];
    float* outp = (float*)d_out;

    float* base;
    cudaGetSymbolAddress((void**)&base, g_scratch);
    float* gq   = base;
    float* gk   = base + (4u  << 20);
    float* gv   = base + (8u  << 20);
    float* grp  = base + (12u << 20);
    float* gatt = base + (13u << 20);
    float* go   = base + (17u << 20);

    cudaFuncSetAttribute(attn_kernel, cudaFuncAttributeMaxDynamicSharedMemorySize,
                         ATTN_SMEM_BYTES);
    cudaFuncSetAttribute(tgemm_kernel, cudaFuncAttributeMaxDynamicSharedMemorySize,
                         GEMM_SMEM_BYTES);

    dim3 gBig(EMB / 128, (BATCH * LSEQ) / 128);  // (8, 32)
    dim3 gR(EMB / 128, LSEQ / 128);              // (8, 8)

    tgemm_kernel<<<gBig, 256, GEMM_SMEM_BYTES>>>(w, Wq, gq, BATCH * LSEQ, EMB, EMB);
    tgemm_kernel<<<gBig, 256, GEMM_SMEM_BYTES>>>(w, Wk, gk, BATCH * LSEQ, EMB, EMB);
    tgemm_kernel<<<gBig, 256, GEMM_SMEM_BYTES>>>(w, Wv, gv, BATCH * LSEQ, EMB, EMB);
    tgemm_kernel<<<gR,   256, GEMM_SMEM_BYTES>>>(r, Wr, grp, LSEQ, EMB, EMB);

    attn_kernel<<<dim3(LSEQ / 64, NH, BATCH), 256, ATTN_SMEM_BYTES>>>(
        gq, gk, gv, grp, rwb, rrb, gatt);

    tgemm_kernel<<<gBig, 256, GEMM_SMEM_BYTES>>>(gatt, Wo, go, BATCH * LSEQ, EMB, EMB);
    ln_kernel<<<BATCH * LSEQ, 256>>>(w, go, gamma, beta, outp);
}

// round 5
// speedup vs baseline: 3.3793x; 1.8913x over previous
#include <cuda_runtime.h>
#include <cuda_bf16.h>
#include <math.h>
#include <cstdint>

// Problem constants
#define BATCH 4
#define LSEQ 1024
#define EMB 1024
#define NH 16
#define DH 64
#define EH (NH*DH)   // 1024

// ---------------- scratch ----------------
// q,k,v: 4M each; rp 1M; att 4M; o 4M => 21M floats
__device__ float g_scratch[21u * 1024u * 1024u];

// ================= common helpers =================
__device__ __forceinline__ uint32_t smem_u32(const void* p) {
    uint32_t a;
    asm("{ .reg .u64 t; cvta.to.shared.u64 t, %1; cvt.u32.u64 %0, t; }" : "=r"(a) : "l"(p));
    return a;
}
__device__ __forceinline__ void cp16(uint32_t dst, const void* src) {
    asm volatile("cp.async.cg.shared.global [%0], [%1], 16;" :: "r"(dst), "l"(src));
}
#define CP_COMMIT()   asm volatile("cp.async.commit_group;" ::: "memory")
#define CP_WAIT1()    asm volatile("cp.async.wait_group 1;" ::: "memory")
#define CP_WAIT_ALL() asm volatile("cp.async.wait_all;" ::: "memory")

__device__ __forceinline__ void mma_tf32(float* c, const uint32_t* a, const uint32_t* b) {
    asm volatile(
        "mma.sync.aligned.m16n8k8.row.col.f32.tf32.tf32.f32 "
        "{%0,%1,%2,%3}, {%4,%5,%6,%7}, {%8,%9}, {%0,%1,%2,%3};"
        : "+f"(c[0]), "+f"(c[1]), "+f"(c[2]), "+f"(c[3])
        : "r"(a[0]), "r"(a[1]), "r"(a[2]), "r"(a[3]), "r"(b[0]), "r"(b[1]));
}

// ================= tf32 GEMM: tile 128x256x32, 3-stage cp.async =================
// All our GEMMs have K = N_ld = 1024 (A row stride K, C row stride 1024).
#define GK 1024
#define GN 1024
#define GBM 128
#define GBN 256
#define GBK 32
#define NSTG 3
#define APAD 36
#define BPAD 264
#define A_STG (GBM * APAD)             // 4608 floats
#define B_STG (GBK * BPAD)             // 8448 floats
#define STG_FLOATS (A_STG + B_STG)     // 13056
#define GEMM_SMEM_BYTES (NSTG * STG_FLOATS * 4)   // 156672 B

__device__ __forceinline__ void gemm_tile(const float* __restrict__ A,
                                          const float* __restrict__ B,
                                          float* __restrict__ C,
                                          int m0, int n0, uint32_t* gsm) {
    const uint32_t sb = smem_u32(gsm);
    const int tid = threadIdx.x;
    const int wid = tid >> 5;
    const int lane = tid & 31;
    const int g = lane >> 2;
    const int t = lane & 3;
    const int wm = wid >> 2;       // 0..1 -> m slice of 64
    const int wn = wid & 3;        // 0..3 -> n slice of 64

    const float* Ab = A + (size_t)m0 * GK;
    const float* Bb = B + n0;

    auto issue = [&](int s) {
        const int k0 = s * GBK;
        const uint32_t abase = sb + (uint32_t)((s % NSTG) * STG_FLOATS * 4);
        const uint32_t bbase = abase + A_STG * 4;
        #pragma unroll
        for (int i = 0; i < 4; i++) {               // A: 1024 chunks
            const int idx = tid + 256 * i;
            const int r = idx >> 3;
            const int c = idx & 7;
            cp16(abase + (uint32_t)(r * (APAD * 4) + c * 16),
                 Ab + (size_t)r * GK + k0 + c * 4);
        }
        #pragma unroll
        for (int i = 0; i < 8; i++) {               // B: 2048 chunks
            const int idx = tid + 256 * i;
            const int r = idx >> 6;
            const int c = idx & 63;
            cp16(bbase + (uint32_t)(r * (BPAD * 4) + c * 16),
                 Bb + (size_t)(k0 + r) * GN + c * 4);
        }
        CP_COMMIT();
    };

    float acc[4][8][4];
    #pragma unroll
    for (int mi = 0; mi < 4; mi++)
        #pragma unroll
        for (int ni = 0; ni < 8; ni++)
            #pragma unroll
            for (int r = 0; r < 4; r++) acc[mi][ni][r] = 0.f;

    issue(0);
    issue(1);

    const int nstages = GK / GBK;   // 32
    for (int s = 0; s < nstages; s++) {
        CP_WAIT1();
        __syncthreads();
        if (s + 2 < nstages) issue(s + 2);

        const uint32_t* As = gsm + (s % NSTG) * STG_FLOATS;
        const uint32_t* Bs = As + A_STG;

        #pragma unroll
        for (int kk = 0; kk < GBK; kk += 8) {
            uint32_t af[4][4], bf[8][2];
            #pragma unroll
            for (int mi = 0; mi < 4; mi++) {
                const int row0 = wm * 64 + mi * 16 + g;
                af[mi][0] = As[row0 * APAD + kk + t];
                af[mi][1] = As[(row0 + 8) * APAD + kk + t];
                af[mi][2] = As[row0 * APAD + kk + t + 4];
                af[mi][3] = As[(row0 + 8) * APAD + kk + t + 4];
            }
            #pragma unroll
            for (int ni = 0; ni < 8; ni++) {
                const int col0 = wn * 64 + ni * 8 + g;
                bf[ni][0] = Bs[(kk + t) * BPAD + col0];
                bf[ni][1] = Bs[(kk + t + 4) * BPAD + col0];
            }
            #pragma unroll
            for (int mi = 0; mi < 4; mi++)
                #pragma unroll
                for (int ni = 0; ni < 8; ni++)
                    mma_tf32(acc[mi][ni], af[mi], bf[ni]);
        }
        __syncthreads();
    }

    #pragma unroll
    for (int mi = 0; mi < 4; mi++) {
        const int row0 = m0 + wm * 64 + mi * 16 + g;
        #pragma unroll
        for (int ni = 0; ni < 8; ni++) {
            const int col = n0 + wn * 64 + ni * 8 + 2 * t;
            float2 v0 = {acc[mi][ni][0], acc[mi][ni][1]};
            float2 v1 = {acc[mi][ni][2], acc[mi][ni][3]};
            *(float2*)(C + (size_t)row0 * GN + col) = v0;
            *(float2*)(C + (size_t)(row0 + 8) * GN + col) = v1;
        }
    }
}

// merged projection GEMM: bsel 0..2 -> w @ {Wq,Wk,Wv}; bsel 3 -> r @ Wr (8 m-tiles)
__global__ __launch_bounds__(256, 1)
void tgemm_proj(const float* __restrict__ w, const float* __restrict__ r,
                const float* __restrict__ Wq, const float* __restrict__ Wk,
                const float* __restrict__ Wv, const float* __restrict__ Wr,
                float* __restrict__ Cbase) {
    extern __shared__ uint32_t gsm[];
    const int bsel = blockIdx.x >> 2;
    if (bsel == 3 && blockIdx.y >= 8) return;
    const float* A = (bsel < 3) ? w : r;
    const float* B = (bsel == 0) ? Wq : (bsel == 1) ? Wk : (bsel == 2) ? Wv : Wr;
    float* C = Cbase + (size_t)bsel * (4u << 20);
    gemm_tile(A, B, C, blockIdx.y * GBM, (blockIdx.x & 3) * GBN, gsm);
}

__global__ __launch_bounds__(256, 1)
void tgemm_single(const float* __restrict__ A, const float* __restrict__ B,
                  float* __restrict__ C) {
    extern __shared__ uint32_t gsm[];
    gemm_tile(A, B, C, blockIdx.y * GBM, blockIdx.x * GBN, gsm);
}

// ================= Attention: tf32 MMA flash-causal with fused rel-shift =================
// Per CTA: 64 query rows, one head, one batch. j-tiles of 64.
// S[i][j] = (Q·K^T + bk[j] + E[i][63+j-i] + br[63+j-i]) * 1/32, E = Q @ Rt^T (Rt = rp window)
#define PQ 68     // stride for sQ,sK,sVt,sS,sRt
#define PE 132    // stride for sE
#define OFF_Q   0
#define OFF_K   (OFF_Q  + 64*PQ)    // 4352
#define OFF_VT  (OFF_K  + 64*PQ)    // 8704
#define OFF_RT  (OFF_VT + 64*PQ)    // 13056
#define OFF_E   (OFF_RT + 128*PQ)   // 21760
#define OFF_S   (OFF_E  + 64*PE)    // 30208
#define OFF_BK  (OFF_S  + 64*PQ)    // 34560
#define OFF_BR  (OFF_BK + 64)       // 34624
#define OFF_RWB (OFF_BR + 128)      // 34752
#define OFF_RRB (OFF_RWB + 64)      // 34816
#define OFF_M   (OFF_RRB + 64)      // 34880
#define OFF_L   (OFF_M + 64)        // 34944
#define OFF_C   (OFF_L + 64)        // 35008
#define ATTN_SMEM_FLOATS (OFF_C + 64)
#define ATTN_SMEM_BYTES  (ATTN_SMEM_FLOATS * 4)

__global__ __launch_bounds__(256)
void attn_kernel(const float* __restrict__ q, const float* __restrict__ k,
                 const float* __restrict__ v, const float* __restrict__ rp,
                 const float* __restrict__ rwb, const float* __restrict__ rrb,
                 float* __restrict__ out) {
    extern __shared__ float sm[];
    const uint32_t sb = smem_u32(sm);
    float* sE   = sm + OFF_E;
    float* sS   = sm + OFF_S;
    float* sBK  = sm + OFF_BK;
    float* sBR  = sm + OFF_BR;
    float* sRWB = sm + OFF_RWB;
    float* sRRB = sm + OFF_RRB;
    float* sM   = sm + OFF_M;
    float* sL   = sm + OFF_L;
    float* sC   = sm + OFF_C;
    const uint32_t* Qs  = (const uint32_t*)(sm + OFF_Q);
    const uint32_t* Ks  = (const uint32_t*)(sm + OFF_K);
    const uint32_t* Vts = (const uint32_t*)(sm + OFF_VT);
    const uint32_t* Rts = (const uint32_t*)(sm + OFF_RT);
    const uint32_t* Ss  = (const uint32_t*)(sm + OFF_S);

    const int i0 = blockIdx.x * 64;
    const int n  = blockIdx.y;
    const int b  = blockIdx.z;
    const int tid = threadIdx.x;
    const int wid = tid >> 5;
    const int lane = tid & 31;
    const int g = lane >> 2;
    const int t = lane & 3;
    const int mrow = (wid & 3) * 16;   // m slice
    const int nb32 = (wid >> 2) * 32;  // n slice for G/PV
    const int nb64 = (wid >> 2) * 64;  // n slice for E

    const size_t bq = (size_t)b * LSEQ * EH;

    // Q tile via cp.async (row-major, stride PQ)
    #pragma unroll
    for (int i = 0; i < 4; i++) {
        const int idx = tid + 256 * i;          // 1024 chunks
        const int row = idx >> 4;
        const int c = idx & 15;
        cp16(sb + (uint32_t)((OFF_Q + row * PQ) * 4 + c * 16),
             q + bq + (size_t)(i0 + row) * EH + n * DH + c * 4);
    }
    if (tid < 64) {
        sRWB[tid] = rwb[n * DH + tid];
        sRRB[tid] = rrb[n * DH + tid];
        sM[tid] = -1e30f;
        sL[tid] = 0.f;
    }

    float oacc[4][4];
    #pragma unroll
    for (int ni = 0; ni < 4; ni++)
        #pragma unroll
        for (int rr2 = 0; rr2 < 4; rr2++) oacc[ni][rr2] = 0.f;

    const int il = tid >> 2;        // softmax row
    const int sub = tid & 3;
    const int jb = sub * 16;

    for (int j0 = 0; j0 <= i0; j0 += 64) {
        // ---- loads: K, Rt via cp.async; V transposed scalar ----
        #pragma unroll
        for (int i = 0; i < 4; i++) {
            const int idx = tid + 256 * i;
            const int row = idx >> 4;
            const int c = idx & 15;
            cp16(sb + (uint32_t)((OFF_K + row * PQ) * 4 + c * 16),
                 k + bq + (size_t)(j0 + row) * EH + n * DH + c * 4);
        }
        const int base = 960 - (i0 - j0);
        #pragma unroll
        for (int i = 0; i < 8; i++) {
            const int idx = tid + 256 * i;      // 2048 chunks
            const int w2 = idx >> 4;            // 0..127
            const int c = idx & 15;
            int m = base + w2;
            if (m > 1023) m = 1023;
            cp16(sb + (uint32_t)((OFF_RT + w2 * PQ) * 4 + c * 16),
                 rp + (size_t)m * EH + n * DH + c * 4);
        }
        {
            const int jj = tid & 63;
            const int db = (tid >> 6) * 16;
            const float* vrow = v + bq + (size_t)(j0 + jj) * EH + n * DH;
            #pragma unroll
            for (int c = 0; c < 4; c++) {
                const int d0 = db + c * 4;
                float4 val = *(const float4*)(vrow + d0);
                sm[OFF_VT + (d0 + 0) * PQ + jj] = val.x;
                sm[OFF_VT + (d0 + 1) * PQ + jj] = val.y;
                sm[OFF_VT + (d0 + 2) * PQ + jj] = val.z;
                sm[OFF_VT + (d0 + 3) * PQ + jj] = val.w;
            }
        }
        CP_WAIT_ALL();
        __syncthreads();

        // ---- G = Q @ K^T (64x64) ----
        {
            float gacc[4][4];
            #pragma unroll
            for (int ni = 0; ni < 4; ni++)
                #pragma unroll
                for (int rr2 = 0; rr2 < 4; rr2++) gacc[ni][rr2] = 0.f;
            #pragma unroll
            for (int kk = 0; kk < 64; kk += 8) {
                uint32_t af[4];
                af[0] = Qs[(mrow + g) * PQ + kk + t];
                af[1] = Qs[(mrow + g + 8) * PQ + kk + t];
                af[2] = Qs[(mrow + g) * PQ + kk + t + 4];
                af[3] = Qs[(mrow + g + 8) * PQ + kk + t + 4];
                #pragma unroll
                for (int ni = 0; ni < 4; ni++) {
                    uint32_t bf[2];
                    const int col0 = nb32 + ni * 8 + g;
                    bf[0] = Ks[col0 * PQ + kk + t];
                    bf[1] = Ks[col0 * PQ + kk + t + 4];
                    mma_tf32(gacc[ni], af, bf);
                }
            }
            #pragma unroll
            for (int ni = 0; ni < 4; ni++) {
                const int col = nb32 + ni * 8 + 2 * t;
                *(float2*)&sS[(mrow + g) * PQ + col] = make_float2(gacc[ni][0], gacc[ni][1]);
                *(float2*)&sS[(mrow + g + 8) * PQ + col] = make_float2(gacc[ni][2], gacc[ni][3]);
            }
        }

        // ---- E = Q @ Rt^T (64x128) ----
        {
            float eacc[8][4];
            #pragma unroll
            for (int ni = 0; ni < 8; ni++)
                #pragma unroll
                for (int rr2 = 0; rr2 < 4; rr2++) eacc[ni][rr2] = 0.f;
            #pragma unroll
            for (int kk = 0; kk < 64; kk += 8) {
                uint32_t af[4];
                af[0] = Qs[(mrow + g) * PQ + kk + t];
                af[1] = Qs[(mrow + g + 8) * PQ + kk + t];
                af[2] = Qs[(mrow + g) * PQ + kk + t + 4];
                af[3] = Qs[(mrow + g + 8) * PQ + kk + t + 4];
                #pragma unroll
                for (int ni = 0; ni < 8; ni++) {
                    uint32_t bf[2];
                    const int col0 = nb64 + ni * 8 + g;
                    bf[0] = Rts[col0 * PQ + kk + t];
                    bf[1] = Rts[col0 * PQ + kk + t + 4];
                    mma_tf32(eacc[ni], af, bf);
                }
            }
            #pragma unroll
            for (int ni = 0; ni < 8; ni++) {
                const int col = nb64 + ni * 8 + 2 * t;
                *(float2*)&sE[(mrow + g) * PE + col] = make_float2(eacc[ni][0], eacc[ni][1]);
                *(float2*)&sE[(mrow + g + 8) * PE + col] = make_float2(eacc[ni][2], eacc[ni][3]);
            }
        }

        // ---- bias vectors bk[j] = rwb.K_j, br[w] = rrb.Rt_w ----
        if (tid < 64) {
            float s = 0.f;
            const float* kr = sm + OFF_K + tid * PQ;
            #pragma unroll 16
            for (int d = 0; d < 64; d++) s += sRWB[d] * kr[d];
            sBK[tid] = s;
        } else if (tid < 191) {
            const int w2 = tid - 64;
            float s = 0.f;
            const float* rr2 = sm + OFF_RT + w2 * PQ;
            #pragma unroll 16
            for (int d = 0; d < 64; d++) s += sRRB[d] * rr2[d];
            sBR[w2] = s;
        }
        __syncthreads();

        // ---- combine + online softmax (4 threads per row) ----
        {
            float rs[16];
            float mx = -1e30f;
            #pragma unroll
            for (int c = 0; c < 16; c++) {
                const int jl = jb + c;
                const int w2 = 63 + jl - il;
                float s = (sS[il * PQ + jl] + sBK[jl] + sE[il * PE + w2] + sBR[w2]) * 0.03125f;
                if (j0 + jl > i0 + il) s = -1e30f;
                rs[c] = s;
                mx = fmaxf(mx, s);
            }
            mx = fmaxf(mx, __shfl_xor_sync(0xffffffffu, mx, 1));
            mx = fmaxf(mx, __shfl_xor_sync(0xffffffffu, mx, 2));
            const float mold = sM[il];
            const float m = fmaxf(mx, mold);
            float sum = 0.f;
            #pragma unroll
            for (int c = 0; c < 16; c++) {
                const float p = __expf(rs[c] - m);
                sS[il * PQ + jb + c] = p;
                sum += p;
            }
            sum += __shfl_xor_sync(0xffffffffu, sum, 1);
            sum += __shfl_xor_sync(0xffffffffu, sum, 2);
            if (sub == 0) {
                const float corr = __expf(mold - m);
                sL[il] = sL[il] * corr + sum;
                sM[il] = m;
                sC[il] = corr;
            }
        }
        __syncthreads();

        // ---- O = O*corr + P @ V ----
        {
            const float c0 = sC[mrow + g];
            const float c1 = sC[mrow + g + 8];
            #pragma unroll
            for (int ni = 0; ni < 4; ni++) {
                oacc[ni][0] *= c0; oacc[ni][1] *= c0;
                oacc[ni][2] *= c1; oacc[ni][3] *= c1;
            }
            #pragma unroll
            for (int kk = 0; kk < 64; kk += 8) {
                uint32_t af[4];
                af[0] = Ss[(mrow + g) * PQ + kk + t];
                af[1] = Ss[(mrow + g + 8) * PQ + kk + t];
                af[2] = Ss[(mrow + g) * PQ + kk + t + 4];
                af[3] = Ss[(mrow + g + 8) * PQ + kk + t + 4];
                #pragma unroll
                for (int ni = 0; ni < 4; ni++) {
                    uint32_t bf[2];
                    const int col0 = nb32 + ni * 8 + g;
                    bf[0] = Vts[col0 * PQ + kk + t];
                    bf[1] = Vts[col0 * PQ + kk + t + 4];
                    mma_tf32(oacc[ni], af, bf);
                }
            }
        }
        __syncthreads();
    }

    // ---- finalize ----
    const float inv0 = 1.f / sL[mrow + g];
    const float inv1 = 1.f / sL[mrow + g + 8];
    const int gi0 = i0 + mrow + g;
    #pragma unroll
    for (int ni = 0; ni < 4; ni++) {
        const int col = nb32 + ni * 8 + 2 * t;
        *(float2*)(out + bq + (size_t)gi0 * EH + n * DH + col) =
            make_float2(oacc[ni][0] * inv0, oacc[ni][1] * inv0);
        *(float2*)(out + bq + (size_t)(gi0 + 8) * EH + n * DH + col) =
            make_float2(oacc[ni][2] * inv1, oacc[ni][3] * inv1);
    }
}

// ---------------- Residual + LayerNorm ----------------
__global__ __launch_bounds__(256)
void ln_kernel(const float* __restrict__ w, const float* __restrict__ o,
               const float* __restrict__ gamma, const float* __restrict__ beta,
               float* __restrict__ out) {
    __shared__ float sh[16];
    __shared__ float mu_s, rstd_s;
    const int row = blockIdx.x;
    const int tid = threadIdx.x;
    const float* wr = w + (size_t)row * EMB;
    const float* orr = o + (size_t)row * EMB;

    float4 xw = *(const float4*)(wr + tid * 4);
    float4 xo = *(const float4*)(orr + tid * 4);
    float x0 = xw.x + xo.x, x1 = xw.y + xo.y, x2 = xw.z + xo.z, x3 = xw.w + xo.w;
    float s = x0 + x1 + x2 + x3;
    float ss = x0 * x0 + x1 * x1 + x2 * x2 + x3 * x3;

    #pragma unroll
    for (int off = 16; off; off >>= 1) {
        s  += __shfl_xor_sync(0xffffffffu, s, off);
        ss += __shfl_xor_sync(0xffffffffu, ss, off);
    }
    if ((tid & 31) == 0) {
        sh[tid >> 5] = s;
        sh[8 + (tid >> 5)] = ss;
    }
    __syncthreads();
    if (tid == 0) {
        float S = 0.f, SS = 0.f;
        #pragma unroll
        for (int i = 0; i < 8; i++) { S += sh[i]; SS += sh[8 + i]; }
        float mu = S * (1.f / 1024.f);
        float var = SS * (1.f / 1024.f) - mu * mu;
        mu_s = mu;
        rstd_s = rsqrtf(var + 1e-3f);
    }
    __syncthreads();

    float mu = mu_s, rstd = rstd_s;
    float4 g4 = *(const float4*)(gamma + tid * 4);
    float4 b4 = *(const float4*)(beta + tid * 4);
    float4 y;
    y.x = (x0 - mu) * rstd * g4.x + b4.x;
    y.y = (x1 - mu) * rstd * g4.y + b4.y;
    y.z = (x2 - mu) * rstd * g4.z + b4.z;
    y.w = (x3 - mu) * rstd * g4.w + b4.w;
    *(float4*)(out + (size_t)row * EMB + tid * 4) = y;
}

// ---------------- launch ----------------
extern "C" void kernel_launch(void* const* d_in, const int* in_sizes, int n_in,
                              void* d_out, int out_size) {
    const float* w     = (const float*)d_in[0];
    const float* r     = (const float*)d_in[1];
    const float* rwb   = (const float*)d_in[2];
    const float* rrb   = (const float*)d_in[3];
    // d_in[4] = attn_mask (causal, analytic)
    const float* Wq    = (const float*)d_in[5];
    const float* Wk    = (const float*)d_in[6];
    const float* Wv    = (const float*)d_in[7];
    const float* Wr    = (const float*)d_in[8];
    const float* Wo    = (const float*)d_in[9];
    const float* gamma = (const float*)d_in[10];
    const float* beta  = (const float*)d_in[11];
    float* outp = (float*)d_out;

    float* base;
    cudaGetSymbolAddress((void**)&base, g_scratch);
    float* gq   = base;                    // bsel 0
    float* gk   = base + (4u  << 20);      // bsel 1
    float* gv   = base + (8u  << 20);      // bsel 2
    float* grp  = base + (12u << 20);      // bsel 3
    float* gatt = base + (13u << 20);
    float* go   = base + (17u << 20);

    cudaFuncSetAttribute(attn_kernel, cudaFuncAttributeMaxDynamicSharedMemorySize,
                         ATTN_SMEM_BYTES);
    cudaFuncSetAttribute(tgemm_proj, cudaFuncAttributeMaxDynamicSharedMemorySize,
                         GEMM_SMEM_BYTES);
    cudaFuncSetAttribute(tgemm_single, cudaFuncAttributeMaxDynamicSharedMemorySize,
                         GEMM_SMEM_BYTES);

    // merged projections: grid.x = 4 bsel * 4 n-tiles, grid.y = 32 m-tiles (bsel 3 uses 8)
    tgemm_proj<<<dim3(16, 32), 256, GEMM_SMEM_BYTES>>>(w, r, Wq, Wk, Wv, Wr, base);

    attn_kernel<<<dim3(LSEQ / 64, NH, BATCH), 256, ATTN_SMEM_BYTES>>>(
        gq, gk, gv, grp, rwb, rrb, gatt);

    tgemm_single<<<dim3(EMB / GBN, (BATCH * LSEQ) / GBM), 256, GEMM_SMEM_BYTES>>>(gatt, Wo, go);
    ln_kernel<<<BATCH * LSEQ, 256>>>(w, go, gamma, beta, outp);
}

// round 6
// speedup vs baseline: 3.4216x; 1.0125x over previous
#include <cuda_runtime.h>
#include <cuda_bf16.h>
#include <math.h>
#include <cstdint>

// Problem constants
#define BATCH 4
#define LSEQ 1024
#define EMB 1024
#define NH 16
#define DH 64
#define EH (NH*DH)   // 1024

// ---------------- scratch ----------------
__device__ float g_scratch[21u * 1024u * 1024u];

// ================= common helpers =================
__device__ __forceinline__ uint32_t smem_u32(const void* p) {
    uint32_t a;
    asm("{ .reg .u64 t; cvta.to.shared.u64 t, %1; cvt.u32.u64 %0, t; }" : "=r"(a) : "l"(p));
    return a;
}
__device__ __forceinline__ void cp16(uint32_t dst, const void* src) {
    asm volatile("cp.async.cg.shared.global [%0], [%1], 16;" :: "r"(dst), "l"(src));
}
#define CP_COMMIT()   asm volatile("cp.async.commit_group;" ::: "memory")
#define CP_WAIT1()    asm volatile("cp.async.wait_group 1;" ::: "memory")
#define CP_WAIT_ALL() asm volatile("cp.async.wait_all;" ::: "memory")

__device__ __forceinline__ void mma_tf32(float* c, const uint32_t* a, const uint32_t* b) {
    asm volatile(
        "mma.sync.aligned.m16n8k8.row.col.f32.tf32.tf32.f32 "
        "{%0,%1,%2,%3}, {%4,%5,%6,%7}, {%8,%9}, {%0,%1,%2,%3};"
        : "+f"(c[0]), "+f"(c[1]), "+f"(c[2]), "+f"(c[3])
        : "r"(a[0]), "r"(a[1]), "r"(a[2]), "r"(a[3]), "r"(b[0]), "r"(b[1]));
}

// ================= tf32 GEMM: tile 128x256x32, 3-stage cp.async =================
#define GK 1024
#define GN 1024
#define GBM 128
#define GBN 256
#define GBK 32
#define NSTG 3
#define APAD 36
#define BPAD 264
#define A_STG (GBM * APAD)
#define B_STG (GBK * BPAD)
#define STG_FLOATS (A_STG + B_STG)
#define GEMM_SMEM_BYTES (NSTG * STG_FLOATS * 4)

__device__ __forceinline__ void gemm_tile(const float* __restrict__ A,
                                          const float* __restrict__ B,
                                          float* __restrict__ C,
                                          int m0, int n0, uint32_t* gsm) {
    const uint32_t sb = smem_u32(gsm);
    const int tid = threadIdx.x;
    const int wid = tid >> 5;
    const int lane = tid & 31;
    const int g = lane >> 2;
    const int t = lane & 3;
    const int wm = wid >> 2;
    const int wn = wid & 3;

    const float* Ab = A + (size_t)m0 * GK;
    const float* Bb = B + n0;

    auto issue = [&](int s) {
        const int k0 = s * GBK;
        const uint32_t abase = sb + (uint32_t)((s % NSTG) * STG_FLOATS * 4);
        const uint32_t bbase = abase + A_STG * 4;
        #pragma unroll
        for (int i = 0; i < 4; i++) {
            const int idx = tid + 256 * i;
            const int r = idx >> 3;
            const int c = idx & 7;
            cp16(abase + (uint32_t)(r * (APAD * 4) + c * 16),
                 Ab + (size_t)r * GK + k0 + c * 4);
        }
        #pragma unroll
        for (int i = 0; i < 8; i++) {
            const int idx = tid + 256 * i;
            const int r = idx >> 6;
            const int c = idx & 63;
            cp16(bbase + (uint32_t)(r * (BPAD * 4) + c * 16),
                 Bb + (size_t)(k0 + r) * GN + c * 4);
        }
        CP_COMMIT();
    };

    float acc[4][8][4];
    #pragma unroll
    for (int mi = 0; mi < 4; mi++)
        #pragma unroll
        for (int ni = 0; ni < 8; ni++)
            #pragma unroll
            for (int r = 0; r < 4; r++) acc[mi][ni][r] = 0.f;

    issue(0);
    issue(1);

    const int nstages = GK / GBK;
    for (int s = 0; s < nstages; s++) {
        CP_WAIT1();
        __syncthreads();
        if (s + 2 < nstages) issue(s + 2);

        const uint32_t* As = gsm + (s % NSTG) * STG_FLOATS;
        const uint32_t* Bs = As + A_STG;

        #pragma unroll
        for (int kk = 0; kk < GBK; kk += 8) {
            uint32_t af[4][4], bf[8][2];
            #pragma unroll
            for (int mi = 0; mi < 4; mi++) {
                const int row0 = wm * 64 + mi * 16 + g;
                af[mi][0] = As[row0 * APAD + kk + t];
                af[mi][1] = As[(row0 + 8) * APAD + kk + t];
                af[mi][2] = As[row0 * APAD + kk + t + 4];
                af[mi][3] = As[(row0 + 8) * APAD + kk + t + 4];
            }
            #pragma unroll
            for (int ni = 0; ni < 8; ni++) {
                const int col0 = wn * 64 + ni * 8 + g;
                bf[ni][0] = Bs[(kk + t) * BPAD + col0];
                bf[ni][1] = Bs[(kk + t + 4) * BPAD + col0];
            }
            #pragma unroll
            for (int mi = 0; mi < 4; mi++)
                #pragma unroll
                for (int ni = 0; ni < 8; ni++)
                    mma_tf32(acc[mi][ni], af[mi], bf[ni]);
        }
        __syncthreads();
    }

    #pragma unroll
    for (int mi = 0; mi < 4; mi++) {
        const int row0 = m0 + wm * 64 + mi * 16 + g;
        #pragma unroll
        for (int ni = 0; ni < 8; ni++) {
            const int col = n0 + wn * 64 + ni * 8 + 2 * t;
            float2 v0 = {acc[mi][ni][0], acc[mi][ni][1]};
            float2 v1 = {acc[mi][ni][2], acc[mi][ni][3]};
            *(float2*)(C + (size_t)row0 * GN + col) = v0;
            *(float2*)(C + (size_t)(row0 + 8) * GN + col) = v1;
        }
    }
}

__global__ __launch_bounds__(256, 1)
void tgemm_proj(const float* __restrict__ w, const float* __restrict__ r,
                const float* __restrict__ Wq, const float* __restrict__ Wk,
                const float* __restrict__ Wv, const float* __restrict__ Wr,
                float* __restrict__ Cbase) {
    extern __shared__ uint32_t gsm[];
    const int bsel = blockIdx.x >> 2;
    if (bsel == 3 && blockIdx.y >= 8) return;
    const float* A = (bsel < 3) ? w : r;
    const float* B = (bsel == 0) ? Wq : (bsel == 1) ? Wk : (bsel == 2) ? Wv : Wr;
    float* C = Cbase + (size_t)bsel * (4u << 20);
    gemm_tile(A, B, C, blockIdx.y * GBM, (blockIdx.x & 3) * GBN, gsm);
}

__global__ __launch_bounds__(256, 1)
void tgemm_single(const float* __restrict__ A, const float* __restrict__ B,
                  float* __restrict__ C) {
    extern __shared__ uint32_t gsm[];
    gemm_tile(A, B, C, blockIdx.y * GBM, blockIdx.x * GBN, gsm);
}

// ================= Attention: pair-balanced, double-buffered K/Rt =================
#define PQ 68
#define PE 132
#define OFF_Q   0
#define OFF_K   (OFF_Q  + 64*PQ)     // 4352 ; 2 bufs
#define OFF_VT  (OFF_K  + 2*64*PQ)   // 13056
#define OFF_RT  (OFF_VT + 64*PQ)     // 17408 ; 2 bufs
#define OFF_E   (OFF_RT + 2*128*PQ)  // 34816
#define OFF_S   (OFF_E  + 64*PE)     // 43264
#define OFF_BK  (OFF_S  + 64*PQ)     // 47616
#define OFF_BR  (OFF_BK + 64)
#define OFF_RWB (OFF_BR + 128)
#define OFF_RRB (OFF_RWB + 64)
#define OFF_M   (OFF_RRB + 64)
#define OFF_L   (OFF_M + 64)
#define OFF_C   (OFF_L + 64)
#define ATTN_SMEM_FLOATS (OFF_C + 64)
#define ATTN_SMEM_BYTES  (ATTN_SMEM_FLOATS * 4)   // 192512 B

__global__ __launch_bounds__(256)
void attn_kernel(const float* __restrict__ q, const float* __restrict__ k,
                 const float* __restrict__ v, const float* __restrict__ rp,
                 const float* __restrict__ rwb, const float* __restrict__ rrb,
                 float* __restrict__ out) {
    extern __shared__ float sm[];
    const uint32_t sb = smem_u32(sm);
    float* sE   = sm + OFF_E;
    float* sS   = sm + OFF_S;
    float* sBK  = sm + OFF_BK;
    float* sBR  = sm + OFF_BR;
    float* sRWB = sm + OFF_RWB;
    float* sRRB = sm + OFF_RRB;
    float* sM   = sm + OFF_M;
    float* sL   = sm + OFF_L;
    float* sC   = sm + OFF_C;
    const uint32_t* Qs  = (const uint32_t*)(sm + OFF_Q);
    const uint32_t* Vts = (const uint32_t*)(sm + OFF_VT);
    const uint32_t* Ss  = (const uint32_t*)(sm + OFF_S);

    const int pair = blockIdx.x;       // 0..7
    const int n  = blockIdx.y;
    const int b  = blockIdx.z;
    const int tid = threadIdx.x;
    const int wid = tid >> 5;
    const int lane = tid & 31;
    const int g = lane >> 2;
    const int t = lane & 3;
    const int mrow = (wid & 3) * 16;
    const int nb32 = (wid >> 2) * 32;
    const int nb64 = (wid >> 2) * 64;

    const size_t bq = (size_t)b * LSEQ * EH;

    const int il = tid >> 2;
    const int sub = tid & 3;
    const int jb = sub * 16;

    if (tid < 64) {
        sRWB[tid] = rwb[n * DH + tid];
        sRRB[tid] = rrb[n * DH + tid];
    }

    for (int half = 0; half < 2; half++) {
        const int itile = (half == 0) ? pair : (15 - pair);
        const int i0 = itile * 64;
        const int ntiles = itile + 1;

        if (tid < 64) { sM[tid] = -1e30f; sL[tid] = 0.f; }

        float oacc[4][4];
        #pragma unroll
        for (int ni = 0; ni < 4; ni++)
            #pragma unroll
            for (int rr2 = 0; rr2 < 4; rr2++) oacc[ni][rr2] = 0.f;

        // issue Q + tile0 (K,Rt) loads -> group 0
        #pragma unroll
        for (int i = 0; i < 4; i++) {
            const int idx = tid + 256 * i;
            const int row = idx >> 4;
            const int c = idx & 15;
            cp16(sb + (uint32_t)((OFF_Q + row * PQ) * 4 + c * 16),
                 q + bq + (size_t)(i0 + row) * EH + n * DH + c * 4);
        }
        {
            // tile 0 K
            #pragma unroll
            for (int i = 0; i < 4; i++) {
                const int idx = tid + 256 * i;
                const int row = idx >> 4;
                const int c = idx & 15;
                cp16(sb + (uint32_t)((OFF_K + row * PQ) * 4 + c * 16),
                     k + bq + (size_t)row * EH + n * DH + c * 4);
            }
            // tile 0 Rt (j0=0): base = 960 - i0
            const int base = 960 - i0;
            #pragma unroll
            for (int i = 0; i < 8; i++) {
                const int idx = tid + 256 * i;
                const int w2 = idx >> 4;
                const int c = idx & 15;
                int m = base + w2;
                if (m > 1023) m = 1023;
                cp16(sb + (uint32_t)((OFF_RT + w2 * PQ) * 4 + c * 16),
                     rp + (size_t)m * EH + n * DH + c * 4);
            }
        }
        CP_COMMIT();

        for (int s = 0; s < ntiles; s++) {
            const int j0 = s * 64;
            const int buf = s & 1;
            const int kofs = OFF_K + buf * 64 * PQ;
            const int rofs = OFF_RT + buf * 128 * PQ;

            // prefetch tile s+1 into other buffer
            if (s + 1 < ntiles) {
                const int nbuf = 1 - buf;
                const int nj0 = j0 + 64;
                #pragma unroll
                for (int i = 0; i < 4; i++) {
                    const int idx = tid + 256 * i;
                    const int row = idx >> 4;
                    const int c = idx & 15;
                    cp16(sb + (uint32_t)((OFF_K + nbuf * 64 * PQ + row * PQ) * 4 + c * 16),
                         k + bq + (size_t)(nj0 + row) * EH + n * DH + c * 4);
                }
                const int base = 960 - (i0 - nj0);
                #pragma unroll
                for (int i = 0; i < 8; i++) {
                    const int idx = tid + 256 * i;
                    const int w2 = idx >> 4;
                    const int c = idx & 15;
                    int m = base + w2;
                    if (m > 1023) m = 1023;
                    cp16(sb + (uint32_t)((OFF_RT + nbuf * 128 * PQ + w2 * PQ) * 4 + c * 16),
                         rp + (size_t)m * EH + n * DH + c * 4);
                }
                CP_COMMIT();
            }

            // V for tile s: scalar load + transpose into VT
            {
                const int jj = tid & 63;
                const int db = (tid >> 6) * 16;
                const float* vrow = v + bq + (size_t)(j0 + jj) * EH + n * DH;
                #pragma unroll
                for (int c = 0; c < 4; c++) {
                    const int d0 = db + c * 4;
                    float4 val = *(const float4*)(vrow + d0);
                    sm[OFF_VT + (d0 + 0) * PQ + jj] = val.x;
                    sm[OFF_VT + (d0 + 1) * PQ + jj] = val.y;
                    sm[OFF_VT + (d0 + 2) * PQ + jj] = val.z;
                    sm[OFF_VT + (d0 + 3) * PQ + jj] = val.w;
                }
            }

            if (s + 1 < ntiles) CP_WAIT1(); else CP_WAIT_ALL();
            __syncthreads();

            const uint32_t* Ks  = (const uint32_t*)(sm + kofs);
            const uint32_t* Rts = (const uint32_t*)(sm + rofs);

            // ---- G = Q @ K^T ----
            {
                float gacc[4][4];
                #pragma unroll
                for (int ni = 0; ni < 4; ni++)
                    #pragma unroll
                    for (int rr2 = 0; rr2 < 4; rr2++) gacc[ni][rr2] = 0.f;
                #pragma unroll
                for (int kk = 0; kk < 64; kk += 8) {
                    uint32_t af[4];
                    af[0] = Qs[(mrow + g) * PQ + kk + t];
                    af[1] = Qs[(mrow + g + 8) * PQ + kk + t];
                    af[2] = Qs[(mrow + g) * PQ + kk + t + 4];
                    af[3] = Qs[(mrow + g + 8) * PQ + kk + t + 4];
                    #pragma unroll
                    for (int ni = 0; ni < 4; ni++) {
                        uint32_t bf[2];
                        const int col0 = nb32 + ni * 8 + g;
                        bf[0] = Ks[col0 * PQ + kk + t];
                        bf[1] = Ks[col0 * PQ + kk + t + 4];
                        mma_tf32(gacc[ni], af, bf);
                    }
                }
                #pragma unroll
                for (int ni = 0; ni < 4; ni++) {
                    const int col = nb32 + ni * 8 + 2 * t;
                    *(float2*)&sS[(mrow + g) * PQ + col] = make_float2(gacc[ni][0], gacc[ni][1]);
                    *(float2*)&sS[(mrow + g + 8) * PQ + col] = make_float2(gacc[ni][2], gacc[ni][3]);
                }
            }

            // ---- E = Q @ Rt^T ----
            {
                float eacc[8][4];
                #pragma unroll
                for (int ni = 0; ni < 8; ni++)
                    #pragma unroll
                    for (int rr2 = 0; rr2 < 4; rr2++) eacc[ni][rr2] = 0.f;
                #pragma unroll
                for (int kk = 0; kk < 64; kk += 8) {
                    uint32_t af[4];
                    af[0] = Qs[(mrow + g) * PQ + kk + t];
                    af[1] = Qs[(mrow + g + 8) * PQ + kk + t];
                    af[2] = Qs[(mrow + g) * PQ + kk + t + 4];
                    af[3] = Qs[(mrow + g + 8) * PQ + kk + t + 4];
                    #pragma unroll
                    for (int ni = 0; ni < 8; ni++) {
                        uint32_t bf[2];
                        const int col0 = nb64 + ni * 8 + g;
                        bf[0] = Rts[col0 * PQ + kk + t];
                        bf[1] = Rts[col0 * PQ + kk + t + 4];
                        mma_tf32(eacc[ni], af, bf);
                    }
                }
                #pragma unroll
                for (int ni = 0; ni < 8; ni++) {
                    const int col = nb64 + ni * 8 + 2 * t;
                    *(float2*)&sE[(mrow + g) * PE + col] = make_float2(eacc[ni][0], eacc[ni][1]);
                    *(float2*)&sE[(mrow + g + 8) * PE + col] = make_float2(eacc[ni][2], eacc[ni][3]);
                }
            }

            // ---- bias vectors ----
            if (tid < 64) {
                float sv = 0.f;
                const float* kr = sm + kofs + tid * PQ;
                #pragma unroll 16
                for (int d = 0; d < 64; d++) sv += sRWB[d] * kr[d];
                sBK[tid] = sv;
            } else if (tid < 191) {
                const int w2 = tid - 64;
                float sv = 0.f;
                const float* rr2 = sm + rofs + w2 * PQ;
                #pragma unroll 16
                for (int d = 0; d < 64; d++) sv += sRRB[d] * rr2[d];
                sBR[w2] = sv;
            }
            __syncthreads();

            // ---- combine + online softmax ----
            {
                float rs[16];
                float mx = -1e30f;
                #pragma unroll
                for (int c = 0; c < 16; c++) {
                    const int jl = jb + c;
                    const int w2 = 63 + jl - il;
                    float sv = (sS[il * PQ + jl] + sBK[jl] + sE[il * PE + w2] + sBR[w2]) * 0.03125f;
                    if (j0 + jl > i0 + il) sv = -1e30f;
                    rs[c] = sv;
                    mx = fmaxf(mx, sv);
                }
                mx = fmaxf(mx, __shfl_xor_sync(0xffffffffu, mx, 1));
                mx = fmaxf(mx, __shfl_xor_sync(0xffffffffu, mx, 2));
                const float mold = sM[il];
                const float m = fmaxf(mx, mold);
                float sum = 0.f;
                #pragma unroll
                for (int c = 0; c < 16; c++) {
                    const float p = __expf(rs[c] - m);
                    sS[il * PQ + jb + c] = p;
                    sum += p;
                }
                sum += __shfl_xor_sync(0xffffffffu, sum, 1);
                sum += __shfl_xor_sync(0xffffffffu, sum, 2);
                if (sub == 0) {
                    const float corr = __expf(mold - m);
                    sL[il] = sL[il] * corr + sum;
                    sM[il] = m;
                    sC[il] = corr;
                }
            }
            __syncthreads();

            // ---- O = O*corr + P @ V ----
            {
                const float c0 = sC[mrow + g];
                const float c1 = sC[mrow + g + 8];
                #pragma unroll
                for (int ni = 0; ni < 4; ni++) {
                    oacc[ni][0] *= c0; oacc[ni][1] *= c0;
                    oacc[ni][2] *= c1; oacc[ni][3] *= c1;
                }
                #pragma unroll
                for (int kk = 0; kk < 64; kk += 8) {
                    uint32_t af[4];
                    af[0] = Ss[(mrow + g) * PQ + kk + t];
                    af[1] = Ss[(mrow + g + 8) * PQ + kk + t];
                    af[2] = Ss[(mrow + g) * PQ + kk + t + 4];
                    af[3] = Ss[(mrow + g + 8) * PQ + kk + t + 4];
                    #pragma unroll
                    for (int ni = 0; ni < 4; ni++) {
                        uint32_t bf[2];
                        const int col0 = nb32 + ni * 8 + g;
                        bf[0] = Vts[col0 * PQ + kk + t];
                        bf[1] = Vts[col0 * PQ + kk + t + 4];
                        mma_tf32(oacc[ni], af, bf);
                    }
                }
            }
            __syncthreads();
        }

        // ---- finalize ----
        const float inv0 = 1.f / sL[mrow + g];
        const float inv1 = 1.f / sL[mrow + g + 8];
        const int gi0 = i0 + mrow + g;
        #pragma unroll
        for (int ni = 0; ni < 4; ni++) {
            const int col = nb32 + ni * 8 + 2 * t;
            *(float2*)(out + bq + (size_t)gi0 * EH + n * DH + col) =
                make_float2(oacc[ni][0] * inv0, oacc[ni][1] * inv0);
            *(float2*)(out + bq + (size_t)(gi0 + 8) * EH + n * DH + col) =
                make_float2(oacc[ni][2] * inv1, oacc[ni][3] * inv1);
        }
        __syncthreads();
    }
}

// ---------------- Residual + LayerNorm ----------------
__global__ __launch_bounds__(256)
void ln_kernel(const float* __restrict__ w, const float* __restrict__ o,
               const float* __restrict__ gamma, const float* __restrict__ beta,
               float* __restrict__ out) {
    __shared__ float sh[16];
    __shared__ float mu_s, rstd_s;
    const int row = blockIdx.x;
    const int tid = threadIdx.x;
    const float* wr = w + (size_t)row * EMB;
    const float* orr = o + (size_t)row * EMB;

    float4 xw = *(const float4*)(wr + tid * 4);
    float4 xo = *(const float4*)(orr + tid * 4);
    float x0 = xw.x + xo.x, x1 = xw.y + xo.y, x2 = xw.z + xo.z, x3 = xw.w + xo.w;
    float s = x0 + x1 + x2 + x3;
    float ss = x0 * x0 + x1 * x1 + x2 * x2 + x3 * x3;

    #pragma unroll
    for (int off = 16; off; off >>= 1) {
        s  += __shfl_xor_sync(0xffffffffu, s, off);
        ss += __shfl_xor_sync(0xffffffffu, ss, off);
    }
    if ((tid & 31) == 0) {
        sh[tid >> 5] = s;
        sh[8 + (tid >> 5)] = ss;
    }
    __syncthreads();
    if (tid == 0) {
        float S = 0.f, SS = 0.f;
        #pragma unroll
        for (int i = 0; i < 8; i++) { S += sh[i]; SS += sh[8 + i]; }
        float mu = S * (1.f / 1024.f);
        float var = SS * (1.f / 1024.f) - mu * mu;
        mu_s = mu;
        rstd_s = rsqrtf(var + 1e-3f);
    }
    __syncthreads();

    float mu = mu_s, rstd = rstd_s;
    float4 g4 = *(const float4*)(gamma + tid * 4);
    float4 b4 = *(const float4*)(beta + tid * 4);
    float4 y;
    y.x = (x0 - mu) * rstd * g4.x + b4.x;
    y.y = (x1 - mu) * rstd * g4.y + b4.y;
    y.z = (x2 - mu) * rstd * g4.z + b4.z;
    y.w = (x3 - mu) * rstd * g4.w + b4.w;
    *(float4*)(out + (size_t)row * EMB + tid * 4) = y;
}

// ---------------- launch ----------------
extern "C" void kernel_launch(void* const* d_in, const int* in_sizes, int n_in,
                              void* d_out, int out_size) {
    const float* w     = (const float*)d_in[0];
    const float* r     = (const float*)d_in[1];
    const float* rwb   = (const float*)d_in[2];
    const float* rrb   = (const float*)d_in[3];
    // d_in[4] = attn_mask (causal, analytic)
    const float* Wq    = (const float*)d_in[5];
    const float* Wk    = (const float*)d_in[6];
    const float* Wv    = (const float*)d_in[7];
    const float* Wr    = (const float*)d_in[8];
    const float* Wo    = (const float*)d_in[9];
    const float* gamma = (const float*)d_in[10];
    const float* beta  = (const float*)d_in[11];
    float* outp = (float*)d_out;

    float* base;
    cudaGetSymbolAddress((void**)&base, g_scratch);
    float* gq   = base;
    float* gk   = base + (4u  << 20);
    float* gv   = base + (8u  << 20);
    float* grp  = base + (12u << 20);
    float* gatt = base + (13u << 20);
    float* go   = base + (17u << 20);

    cudaFuncSetAttribute(attn_kernel, cudaFuncAttributeMaxDynamicSharedMemorySize,
                         ATTN_SMEM_BYTES);
    cudaFuncSetAttribute(tgemm_proj, cudaFuncAttributeMaxDynamicSharedMemorySize,
                         GEMM_SMEM_BYTES);
    cudaFuncSetAttribute(tgemm_single, cudaFuncAttributeMaxDynamicSharedMemorySize,
                         GEMM_SMEM_BYTES);

    tgemm_proj<<<dim3(16, 32), 256, GEMM_SMEM_BYTES>>>(w, r, Wq, Wk, Wv, Wr, base);

    attn_kernel<<<dim3(8, NH, BATCH), 256, ATTN_SMEM_BYTES>>>(
        gq, gk, gv, grp, rwb, rrb, gatt);

    tgemm_single<<<dim3(EMB / GBN, (BATCH * LSEQ) / GBM), 256, GEMM_SMEM_BYTES>>>(gatt, Wo, go);
    ln_kernel<<<BATCH * LSEQ, 256>>>(w, go, gamma, beta, outp);
}

// round 7
// speedup vs baseline: 3.6415x; 1.0643x over previous
#include <cuda_runtime.h>
#include <cuda_bf16.h>
#include <math.h>
#include <cstdint>

// Problem constants
#define BATCH 4
#define LSEQ 1024
#define EMB 1024
#define NH 16
#define DH 64
#define EH (NH*DH)   // 1024

// ---------------- scratch ----------------
__device__ float g_scratch[21u * 1024u * 1024u];

// ================= common helpers =================
__device__ __forceinline__ uint32_t smem_u32(const void* p) {
    uint32_t a;
    asm("{ .reg .u64 t; cvta.to.shared.u64 t, %1; cvt.u32.u64 %0, t; }" : "=r"(a) : "l"(p));
    return a;
}
__device__ __forceinline__ void cp16(uint32_t dst, const void* src) {
    asm volatile("cp.async.cg.shared.global [%0], [%1], 16;" :: "r"(dst), "l"(src));
}
#define CP_COMMIT()   asm volatile("cp.async.commit_group;" ::: "memory")
#define CP_WAIT1()    asm volatile("cp.async.wait_group 1;" ::: "memory")
#define CP_WAIT_ALL() asm volatile("cp.async.wait_all;" ::: "memory")

__device__ __forceinline__ void mma_tf32(float* c, const uint32_t* a, const uint32_t* b) {
    asm volatile(
        "mma.sync.aligned.m16n8k8.row.col.f32.tf32.tf32.f32 "
        "{%0,%1,%2,%3}, {%4,%5,%6,%7}, {%8,%9}, {%0,%1,%2,%3};"
        : "+f"(c[0]), "+f"(c[1]), "+f"(c[2]), "+f"(c[3])
        : "r"(a[0]), "r"(a[1]), "r"(a[2]), "r"(a[3]), "r"(b[0]), "r"(b[1]));
}

// ================= tf32 GEMM: tile 128x256x32, 3-stage cp.async =================
#define GK 1024
#define GN 1024
#define GBM 128
#define GBN 256
#define GBK 32
#define NSTG 3
#define APAD 36
#define BPAD 264
#define A_STG (GBM * APAD)
#define B_STG (GBK * BPAD)
#define STG_FLOATS (A_STG + B_STG)
#define GEMM_SMEM_BYTES (NSTG * STG_FLOATS * 4)

__device__ __forceinline__ void gemm_tile(const float* __restrict__ A,
                                          const float* __restrict__ B,
                                          float* __restrict__ C,
                                          int m0, int n0, uint32_t* gsm) {
    const uint32_t sb = smem_u32(gsm);
    const int tid = threadIdx.x;
    const int wid = tid >> 5;
    const int lane = tid & 31;
    const int g = lane >> 2;
    const int t = lane & 3;
    const int wm = wid >> 2;
    const int wn = wid & 3;

    const float* Ab = A + (size_t)m0 * GK;
    const float* Bb = B + n0;

    auto issue = [&](int s) {
        const int k0 = s * GBK;
        const uint32_t abase = sb + (uint32_t)((s % NSTG) * STG_FLOATS * 4);
        const uint32_t bbase = abase + A_STG * 4;
        #pragma unroll
        for (int i = 0; i < 4; i++) {
            const int idx = tid + 256 * i;
            const int r = idx >> 3;
            const int c = idx & 7;
            cp16(abase + (uint32_t)(r * (APAD * 4) + c * 16),
                 Ab + (size_t)r * GK + k0 + c * 4);
        }
        #pragma unroll
        for (int i = 0; i < 8; i++) {
            const int idx = tid + 256 * i;
            const int r = idx >> 6;
            const int c = idx & 63;
            cp16(bbase + (uint32_t)(r * (BPAD * 4) + c * 16),
                 Bb + (size_t)(k0 + r) * GN + c * 4);
        }
        CP_COMMIT();
    };

    float acc[4][8][4];
    #pragma unroll
    for (int mi = 0; mi < 4; mi++)
        #pragma unroll
        for (int ni = 0; ni < 8; ni++)
            #pragma unroll
            for (int r = 0; r < 4; r++) acc[mi][ni][r] = 0.f;

    issue(0);
    issue(1);

    const int nstages = GK / GBK;
    for (int s = 0; s < nstages; s++) {
        CP_WAIT1();
        __syncthreads();
        if (s + 2 < nstages) issue(s + 2);

        const uint32_t* As = gsm + (s % NSTG) * STG_FLOATS;
        const uint32_t* Bs = As + A_STG;

        #pragma unroll
        for (int kk = 0; kk < GBK; kk += 8) {
            uint32_t af[4][4], bf[8][2];
            #pragma unroll
            for (int mi = 0; mi < 4; mi++) {
                const int row0 = wm * 64 + mi * 16 + g;
                af[mi][0] = As[row0 * APAD + kk + t];
                af[mi][1] = As[(row0 + 8) * APAD + kk + t];
                af[mi][2] = As[row0 * APAD + kk + t + 4];
                af[mi][3] = As[(row0 + 8) * APAD + kk + t + 4];
            }
            #pragma unroll
            for (int ni = 0; ni < 8; ni++) {
                const int col0 = wn * 64 + ni * 8 + g;
                bf[ni][0] = Bs[(kk + t) * BPAD + col0];
                bf[ni][1] = Bs[(kk + t + 4) * BPAD + col0];
            }
            #pragma unroll
            for (int mi = 0; mi < 4; mi++)
                #pragma unroll
                for (int ni = 0; ni < 8; ni++)
                    mma_tf32(acc[mi][ni], af[mi], bf[ni]);
        }
        __syncthreads();
    }

    #pragma unroll
    for (int mi = 0; mi < 4; mi++) {
        const int row0 = m0 + wm * 64 + mi * 16 + g;
        #pragma unroll
        for (int ni = 0; ni < 8; ni++) {
            const int col = n0 + wn * 64 + ni * 8 + 2 * t;
            float2 v0 = {acc[mi][ni][0], acc[mi][ni][1]};
            float2 v1 = {acc[mi][ni][2], acc[mi][ni][3]};
            *(float2*)(C + (size_t)row0 * GN + col) = v0;
            *(float2*)(C + (size_t)(row0 + 8) * GN + col) = v1;
        }
    }
}

__global__ __launch_bounds__(256, 1)
void tgemm_proj(const float* __restrict__ w, const float* __restrict__ r,
                const float* __restrict__ Wq, const float* __restrict__ Wk,
                const float* __restrict__ Wv, const float* __restrict__ Wr,
                float* __restrict__ Cbase) {
    extern __shared__ uint32_t gsm[];
    const int bsel = blockIdx.x >> 2;
    if (bsel == 3 && blockIdx.y >= 8) return;
    const float* A = (bsel < 3) ? w : r;
    const float* B = (bsel == 0) ? Wq : (bsel == 1) ? Wk : (bsel == 2) ? Wv : Wr;
    float* C = Cbase + (size_t)bsel * (4u << 20);
    gemm_tile(A, B, C, blockIdx.y * GBM, (blockIdx.x & 3) * GBN, gsm);
}

__global__ __launch_bounds__(256, 1)
void tgemm_single(const float* __restrict__ A, const float* __restrict__ B,
                  float* __restrict__ C) {
    extern __shared__ uint32_t gsm[];
    gemm_tile(A, B, C, blockIdx.y * GBM, blockIdx.x * GBN, gsm);
}

// ================= Attention: ring-buffered E/Rt reuse =================
// rp window slides by 64/tile; absolute w-coord = 64*s + w2 (w2 in [0,126]).
// E ring: 128 cols, slot = abs & 127. Rt ring: 192 rows, slot = abs mod 192
// (mod 192 so the prefetched 64-row block never overlaps the live window).
#define PQ 68
#define PE 132
#define OFF_Q   0
#define OFF_K   (OFF_Q  + 64*PQ)      // 2 bufs
#define OFF_VT  (OFF_K  + 2*64*PQ)
#define OFF_RT  (OFF_VT + 64*PQ)      // 192-row ring
#define OFF_E   (OFF_RT + 192*PQ)     // 128-col ring
#define OFF_S   (OFF_E  + 64*PE)
#define OFF_BK  (OFF_S  + 64*PQ)
#define OFF_BR  (OFF_BK + 64)         // 128-entry ring
#define OFF_RWB (OFF_BR + 128)
#define OFF_RRB (OFF_RWB + 64)
#define OFF_M   (OFF_RRB + 64)
#define OFF_L   (OFF_M + 64)
#define OFF_C   (OFF_L + 64)
#define ATTN_SMEM_FLOATS (OFF_C + 64)
#define ATTN_SMEM_BYTES  (ATTN_SMEM_FLOATS * 4)   // 175104 B

__global__ __launch_bounds__(256)
void attn_kernel(const float* __restrict__ q, const float* __restrict__ k,
                 const float* __restrict__ v, const float* __restrict__ rp,
                 const float* __restrict__ rwb, const float* __restrict__ rrb,
                 float* __restrict__ out) {
    extern __shared__ float sm[];
    const uint32_t sb = smem_u32(sm);
    float* sE   = sm + OFF_E;
    float* sS   = sm + OFF_S;
    float* sBK  = sm + OFF_BK;
    float* sBR  = sm + OFF_BR;
    float* sRWB = sm + OFF_RWB;
    float* sRRB = sm + OFF_RRB;
    float* sM   = sm + OFF_M;
    float* sL   = sm + OFF_L;
    float* sC   = sm + OFF_C;
    const uint32_t* Qs  = (const uint32_t*)(sm + OFF_Q);
    const uint32_t* Vts = (const uint32_t*)(sm + OFF_VT);
    const uint32_t* Rts = (const uint32_t*)(sm + OFF_RT);
    const uint32_t* Ss  = (const uint32_t*)(sm + OFF_S);

    const int pair = blockIdx.x;       // 0..7
    const int n  = blockIdx.y;
    const int b  = blockIdx.z;
    const int tid = threadIdx.x;
    const int wid = tid >> 5;
    const int lane = tid & 31;
    const int g = lane >> 2;
    const int t = lane & 3;
    const int mrow = (wid & 3) * 16;
    const int nb32 = (wid >> 2) * 32;
    const int nb64 = (wid >> 2) * 64;

    const size_t bq = (size_t)b * LSEQ * EH;

    const int il = tid >> 2;
    const int sub = tid & 3;
    const int jb = sub * 16;

    if (tid < 64) {
        sRWB[tid] = rwb[n * DH + tid];
        sRRB[tid] = rrb[n * DH + tid];
    }

    for (int half = 0; half < 2; half++) {
        const int itile = (half == 0) ? pair : (15 - pair);
        const int i0 = itile * 64;
        const int ntiles = itile + 1;
        const int mw0 = 960 - i0;          // absolute m for w-coord 0

        if (tid < 64) { sM[tid] = -1e30f; sL[tid] = 0.f; }

        float oacc[4][4];
        #pragma unroll
        for (int ni = 0; ni < 4; ni++)
            #pragma unroll
            for (int rr2 = 0; rr2 < 4; rr2++) oacc[ni][rr2] = 0.f;

        // ---- initial loads: Q, K tile0, Rt slots 0..127 ----
        #pragma unroll
        for (int i = 0; i < 4; i++) {
            const int idx = tid + 256 * i;
            const int row = idx >> 4;
            const int c = idx & 15;
            cp16(sb + (uint32_t)((OFF_Q + row * PQ) * 4 + c * 16),
                 q + bq + (size_t)(i0 + row) * EH + n * DH + c * 4);
        }
        #pragma unroll
        for (int i = 0; i < 4; i++) {
            const int idx = tid + 256 * i;
            const int row = idx >> 4;
            const int c = idx & 15;
            cp16(sb + (uint32_t)((OFF_K + row * PQ) * 4 + c * 16),
                 k + bq + (size_t)row * EH + n * DH + c * 4);
        }
        #pragma unroll
        for (int i = 0; i < 8; i++) {
            const int idx = tid + 256 * i;
            const int w2 = idx >> 4;            // 0..127 -> ring slot w2
            const int c = idx & 15;
            int m = mw0 + w2;
            if (m > 1023) m = 1023;
            cp16(sb + (uint32_t)((OFF_RT + w2 * PQ) * 4 + c * 16),
                 rp + (size_t)m * EH + n * DH + c * 4);
        }
        CP_COMMIT();

        for (int s = 0; s < ntiles; s++) {
            const int j0 = s * 64;
            const int buf = s & 1;
            const int kofs = OFF_K + buf * 64 * PQ;
            const int sbase = (s & 1) * 64;              // E/br ring base of window
            const int ebase = (sbase + 64) & 127;        // this tile's new E block
            const int rtnew = ((s + 1) % 3) * 64;        // this tile's new Rt rows

            // ---- prefetch tile s+1: K + 64 new Rt rows ----
            if (s + 1 < ntiles) {
                const int nbuf = 1 - buf;
                const int nj0 = j0 + 64;
                #pragma unroll
                for (int i = 0; i < 4; i++) {
                    const int idx = tid + 256 * i;
                    const int row = idx >> 4;
                    const int c = idx & 15;
                    cp16(sb + (uint32_t)((OFF_K + nbuf * 64 * PQ + row * PQ) * 4 + c * 16),
                         k + bq + (size_t)(nj0 + row) * EH + n * DH + c * 4);
                }
                const int nslot = ((s + 2) % 3) * 64;
                const int mb = mw0 + 64 * s + 128;
                #pragma unroll
                for (int i = 0; i < 4; i++) {
                    const int idx = tid + 256 * i;
                    const int row = idx >> 4;               // 0..63
                    const int c = idx & 15;
                    int m = mb + row;
                    if (m > 1023) m = 1023;
                    cp16(sb + (uint32_t)((OFF_RT + (nslot + row) * PQ) * 4 + c * 16),
                         rp + (size_t)m * EH + n * DH + c * 4);
                }
                CP_COMMIT();
            }

            // V for tile s: scalar load + transpose into VT
            {
                const int jj = tid & 63;
                const int db = (tid >> 6) * 16;
                const float* vrow = v + bq + (size_t)(j0 + jj) * EH + n * DH;
                #pragma unroll
                for (int c = 0; c < 4; c++) {
                    const int d0 = db + c * 4;
                    float4 val = *(const float4*)(vrow + d0);
                    sm[OFF_VT + (d0 + 0) * PQ + jj] = val.x;
                    sm[OFF_VT + (d0 + 1) * PQ + jj] = val.y;
                    sm[OFF_VT + (d0 + 2) * PQ + jj] = val.z;
                    sm[OFF_VT + (d0 + 3) * PQ + jj] = val.w;
                }
            }

            if (s + 1 < ntiles) CP_WAIT1(); else CP_WAIT_ALL();
            __syncthreads();

            const uint32_t* Ks = (const uint32_t*)(sm + kofs);

            // ---- G = Q @ K^T ----
            {
                float gacc[4][4];
                #pragma unroll
                for (int ni = 0; ni < 4; ni++)
                    #pragma unroll
                    for (int rr2 = 0; rr2 < 4; rr2++) gacc[ni][rr2] = 0.f;
                #pragma unroll
                for (int kk = 0; kk < 64; kk += 8) {
                    uint32_t af[4];
                    af[0] = Qs[(mrow + g) * PQ + kk + t];
                    af[1] = Qs[(mrow + g + 8) * PQ + kk + t];
                    af[2] = Qs[(mrow + g) * PQ + kk + t + 4];
                    af[3] = Qs[(mrow + g + 8) * PQ + kk + t + 4];
                    #pragma unroll
                    for (int ni = 0; ni < 4; ni++) {
                        uint32_t bf[2];
                        const int col0 = nb32 + ni * 8 + g;
                        bf[0] = Ks[col0 * PQ + kk + t];
                        bf[1] = Ks[col0 * PQ + kk + t + 4];
                        mma_tf32(gacc[ni], af, bf);
                    }
                }
                #pragma unroll
                for (int ni = 0; ni < 4; ni++) {
                    const int col = nb32 + ni * 8 + 2 * t;
                    *(float2*)&sS[(mrow + g) * PQ + col] = make_float2(gacc[ni][0], gacc[ni][1]);
                    *(float2*)&sS[(mrow + g + 8) * PQ + col] = make_float2(gacc[ni][2], gacc[ni][3]);
                }
            }

            // ---- E: new columns only (s=0: all 128; s>0: 64 new) ----
            if (s == 0) {
                float eacc[8][4];
                #pragma unroll
                for (int ni = 0; ni < 8; ni++)
                    #pragma unroll
                    for (int rr2 = 0; rr2 < 4; rr2++) eacc[ni][rr2] = 0.f;
                #pragma unroll
                for (int kk = 0; kk < 64; kk += 8) {
                    uint32_t af[4];
                    af[0] = Qs[(mrow + g) * PQ + kk + t];
                    af[1] = Qs[(mrow + g + 8) * PQ + kk + t];
                    af[2] = Qs[(mrow + g) * PQ + kk + t + 4];
                    af[3] = Qs[(mrow + g + 8) * PQ + kk + t + 4];
                    #pragma unroll
                    for (int ni = 0; ni < 8; ni++) {
                        uint32_t bf[2];
                        const int col0 = nb64 + ni * 8 + g;      // Rt slot = w
                        bf[0] = Rts[col0 * PQ + kk + t];
                        bf[1] = Rts[col0 * PQ + kk + t + 4];
                        mma_tf32(eacc[ni], af, bf);
                    }
                }
                #pragma unroll
                for (int ni = 0; ni < 8; ni++) {
                    const int col = nb64 + ni * 8 + 2 * t;
                    *(float2*)&sE[(mrow + g) * PE + col] = make_float2(eacc[ni][0], eacc[ni][1]);
                    *(float2*)&sE[(mrow + g + 8) * PE + col] = make_float2(eacc[ni][2], eacc[ni][3]);
                }
            } else {
                float eacc[4][4];
                #pragma unroll
                for (int ni = 0; ni < 4; ni++)
                    #pragma unroll
                    for (int rr2 = 0; rr2 < 4; rr2++) eacc[ni][rr2] = 0.f;
                #pragma unroll
                for (int kk = 0; kk < 64; kk += 8) {
                    uint32_t af[4];
                    af[0] = Qs[(mrow + g) * PQ + kk + t];
                    af[1] = Qs[(mrow + g + 8) * PQ + kk + t];
                    af[2] = Qs[(mrow + g) * PQ + kk + t + 4];
                    af[3] = Qs[(mrow + g + 8) * PQ + kk + t + 4];
                    #pragma unroll
                    for (int ni = 0; ni < 4; ni++) {
                        uint32_t bf[2];
                        const int colb = nb32 + ni * 8 + g;      // 0..63 within new block
                        bf[0] = Rts[(rtnew + colb) * PQ + kk + t];
                        bf[1] = Rts[(rtnew + colb) * PQ + kk + t + 4];
                        mma_tf32(eacc[ni], af, bf);
                    }
                }
                #pragma unroll
                for (int ni = 0; ni < 4; ni++) {
                    const int col = ebase + nb32 + ni * 8 + 2 * t;
                    *(float2*)&sE[(mrow + g) * PE + col] = make_float2(eacc[ni][0], eacc[ni][1]);
                    *(float2*)&sE[(mrow + g + 8) * PE + col] = make_float2(eacc[ni][2], eacc[ni][3]);
                }
            }

            // ---- bias vectors: bk (64) + new br block ----
            if (tid < 64) {
                float sv = 0.f;
                const float* kr = sm + kofs + tid * PQ;
                #pragma unroll 16
                for (int d = 0; d < 64; d++) sv += sRWB[d] * kr[d];
                sBK[tid] = sv;
            } else if (s == 0 ? (tid < 192) : (tid < 128)) {
                const int d0 = tid - 64;                 // s=0: 0..127, else 0..63
                const int eslot = (s == 0) ? d0 : (ebase + d0);
                const int rtrow = (s == 0) ? d0 : (rtnew + d0);
                float sv = 0.f;
                const float* rr2 = sm + OFF_RT + rtrow * PQ;
                #pragma unroll 16
                for (int d = 0; d < 64; d++) sv += sRRB[d] * rr2[d];
                sBR[eslot] = sv;
            }
            __syncthreads();

            // ---- combine + online softmax (ring reads) ----
            {
                float rs[16];
                float mx = -1e30f;
                #pragma unroll
                for (int c = 0; c < 16; c++) {
                    const int jl = jb + c;
                    const int w2 = 63 + jl - il;
                    const int slot = (sbase + w2) & 127;
                    float sv = (sS[il * PQ + jl] + sBK[jl] + sE[il * PE + slot] + sBR[slot]) * 0.03125f;
                    if (j0 + jl > i0 + il) sv = -1e30f;
                    rs[c] = sv;
                    mx = fmaxf(mx, sv);
                }
                mx = fmaxf(mx, __shfl_xor_sync(0xffffffffu, mx, 1));
                mx = fmaxf(mx, __shfl_xor_sync(0xffffffffu, mx, 2));
                const float mold = sM[il];
                const float m = fmaxf(mx, mold);
                float sum = 0.f;
                #pragma unroll
                for (int c = 0; c < 16; c++) {
                    const float p = __expf(rs[c] - m);
                    sS[il * PQ + jb + c] = p;
                    sum += p;
                }
                sum += __shfl_xor_sync(0xffffffffu, sum, 1);
                sum += __shfl_xor_sync(0xffffffffu, sum, 2);
                if (sub == 0) {
                    const float corr = __expf(mold - m);
                    sL[il] = sL[il] * corr + sum;
                    sM[il] = m;
                    sC[il] = corr;
                }
            }
            __syncthreads();

            // ---- O = O*corr + P @ V ----
            {
                const float c0 = sC[mrow + g];
                const float c1 = sC[mrow + g + 8];
                #pragma unroll
                for (int ni = 0; ni < 4; ni++) {
                    oacc[ni][0] *= c0; oacc[ni][1] *= c0;
                    oacc[ni][2] *= c1; oacc[ni][3] *= c1;
                }
                #pragma unroll
                for (int kk = 0; kk < 64; kk += 8) {
                    uint32_t af[4];
                    af[0] = Ss[(mrow + g) * PQ + kk + t];
                    af[1] = Ss[(mrow + g + 8) * PQ + kk + t];
                    af[2] = Ss[(mrow + g) * PQ + kk + t + 4];
                    af[3] = Ss[(mrow + g + 8) * PQ + kk + t + 4];
                    #pragma unroll
                    for (int ni = 0; ni < 4; ni++) {
                        uint32_t bf[2];
                        const int col0 = nb32 + ni * 8 + g;
                        bf[0] = Vts[col0 * PQ + kk + t];
                        bf[1] = Vts[col0 * PQ + kk + t + 4];
                        mma_tf32(oacc[ni], af, bf);
                    }
                }
            }
            __syncthreads();
        }

        // ---- finalize ----
        const float inv0 = 1.f / sL[mrow + g];
        const float inv1 = 1.f / sL[mrow + g + 8];
        const int gi0 = i0 + mrow + g;
        #pragma unroll
        for (int ni = 0; ni < 4; ni++) {
            const int col = nb32 + ni * 8 + 2 * t;
            *(float2*)(out + bq + (size_t)gi0 * EH + n * DH + col) =
                make_float2(oacc[ni][0] * inv0, oacc[ni][1] * inv0);
            *(float2*)(out + bq + (size_t)(gi0 + 8) * EH + n * DH + col) =
                make_float2(oacc[ni][2] * inv1, oacc[ni][3] * inv1);
        }
        __syncthreads();
    }
}

// ---------------- Residual + LayerNorm ----------------
__global__ __launch_bounds__(256)
void ln_kernel(const float* __restrict__ w, const float* __restrict__ o,
               const float* __restrict__ gamma, const float* __restrict__ beta,
               float* __restrict__ out) {
    __shared__ float sh[16];
    __shared__ float mu_s, rstd_s;
    const int row = blockIdx.x;
    const int tid = threadIdx.x;
    const float* wr = w + (size_t)row * EMB;
    const float* orr = o + (size_t)row * EMB;

    float4 xw = *(const float4*)(wr + tid * 4);
    float4 xo = *(const float4*)(orr + tid * 4);
    float x0 = xw.x + xo.x, x1 = xw.y + xo.y, x2 = xw.z + xo.z, x3 = xw.w + xo.w;
    float s = x0 + x1 + x2 + x3;
    float ss = x0 * x0 + x1 * x1 + x2 * x2 + x3 * x3;

    #pragma unroll
    for (int off = 16; off; off >>= 1) {
        s  += __shfl_xor_sync(0xffffffffu, s, off);
        ss += __shfl_xor_sync(0xffffffffu, ss, off);
    }
    if ((tid & 31) == 0) {
        sh[tid >> 5] = s;
        sh[8 + (tid >> 5)] = ss;
    }
    __syncthreads();
    if (tid == 0) {
        float S = 0.f, SS = 0.f;
        #pragma unroll
        for (int i = 0; i < 8; i++) { S += sh[i]; SS += sh[8 + i]; }
        float mu = S * (1.f / 1024.f);
        float var = SS * (1.f / 1024.f) - mu * mu;
        mu_s = mu;
        rstd_s = rsqrtf(var + 1e-3f);
    }
    __syncthreads();

    float mu = mu_s, rstd = rstd_s;
    float4 g4 = *(const float4*)(gamma + tid * 4);
    float4 b4 = *(const float4*)(beta + tid * 4);
    float4 y;
    y.x = (x0 - mu) * rstd * g4.x + b4.x;
    y.y = (x1 - mu) * rstd * g4.y + b4.y;
    y.z = (x2 - mu) * rstd * g4.z + b4.z;
    y.w = (x3 - mu) * rstd * g4.w + b4.w;
    *(float4*)(out + (size_t)row * EMB + tid * 4) = y;
}

// ---------------- launch ----------------
extern "C" void kernel_launch(void* const* d_in, const int* in_sizes, int n_in,
                              void* d_out, int out_size) {
    const float* w     = (const float*)d_in[0];
    const float* r     = (const float*)d_in[1];
    const float* rwb   = (const float*)d_in[2];
    const float* rrb   = (const float*)d_in[3];
    // d_in[4] = attn_mask (causal, analytic)
    const float* Wq    = (const float*)d_in[5];
    const float* Wk    = (const float*)d_in[6];
    const float* Wv    = (const float*)d_in[7];
    const float* Wr    = (const float*)d_in[8];
    const float* Wo    = (const float*)d_in[9];
    const float* gamma = (const float*)d_in[10];
    const float* beta  = (const float*)d_in[11];
    float* outp = (float*)d_out;

    float* base;
    cudaGetSymbolAddress((void**)&base, g_scratch);
    float* gq   = base;
    float* gk   = base + (4u  << 20);
    float* gv   = base + (8u  << 20);
    float* grp  = base + (12u << 20);
    float* gatt = base + (13u << 20);
    float* go   = base + (17u << 20);

    cudaFuncSetAttribute(attn_kernel, cudaFuncAttributeMaxDynamicSharedMemorySize,
                         ATTN_SMEM_BYTES);
    cudaFuncSetAttribute(tgemm_proj, cudaFuncAttributeMaxDynamicSharedMemorySize,
                         GEMM_SMEM_BYTES);
    cudaFuncSetAttribute(tgemm_single, cudaFuncAttributeMaxDynamicSharedMemorySize,
                         GEMM_SMEM_BYTES);

    tgemm_proj<<<dim3(16, 32), 256, GEMM_SMEM_BYTES>>>(w, r, Wq, Wk, Wv, Wr, base);

    attn_kernel<<<dim3(8, NH, BATCH), 256, ATTN_SMEM_BYTES>>>(
        gq, gk, gv, grp, rwb, rrb, gatt);

    tgemm_single<<<dim3(EMB / GBN, (BATCH * LSEQ) / GBM), 256, GEMM_SMEM_BYTES>>>(gatt, Wo, go);
    ln_kernel<<<BATCH * LSEQ, 256>>>(w, go, gamma, beta, outp);
}